// round 4
// baseline (speedup 1.0000x reference)
#include <cuda_runtime.h>
#include <cuda_bf16.h>
#include <math.h>
#include <stdint.h>

#define B_   2
#define N_   4096
#define E_   1024
#define H_   16
#define HD_  64
#define BH_  32
#define M_   8192

// ==================== device scratch ====================
__device__ __align__(16) __nv_bfloat16 g_whi[4][E_ * E_];
__device__ __align__(16) __nv_bfloat16 g_wlo[4][E_ * E_];
__device__ __align__(16) __nv_bfloat16 g_xhi[M_ * E_];
__device__ __align__(16) __nv_bfloat16 g_xlo[M_ * E_];
__device__ __align__(16) __nv_bfloat16 g_ahi[M_ * E_];
__device__ __align__(16) __nv_bfloat16 g_alo[M_ * E_];
__device__ float g_q[M_ * E_];
__device__ float g_k[M_ * E_];
__device__ float g_v[M_ * E_];
__device__ float g_attn[M_ * E_];
__device__ int   g_sidx[3][B_][N_];

// ==================== helpers ====================
__device__ __forceinline__ uint32_t smem_u32(const void* p) {
    uint32_t a;
    asm("{ .reg .u64 t; cvta.to.shared.u64 t, %1; cvt.u32.u64 %0, t; }" : "=r"(a) : "l"(p));
    return a;
}
__device__ __forceinline__ void cp16(uint32_t dst, const void* src) {
    asm volatile("cp.async.cg.shared.global [%0], [%1], 16;" :: "r"(dst), "l"(src));
}
#define CP_COMMIT() asm volatile("cp.async.commit_group;" ::: "memory")
#define CP_WAIT(n)  asm volatile("cp.async.wait_group %0;" :: "n"(n) : "memory")

__device__ __forceinline__ void mma16816(float* c, const uint32_t* a, uint32_t b0, uint32_t b1) {
    asm volatile(
        "mma.sync.aligned.m16n8k16.row.col.f32.bf16.bf16.f32 "
        "{%0,%1,%2,%3}, {%4,%5,%6,%7}, {%8,%9}, {%0,%1,%2,%3};"
        : "+f"(c[0]), "+f"(c[1]), "+f"(c[2]), "+f"(c[3])
        : "r"(a[0]), "r"(a[1]), "r"(a[2]), "r"(a[3]), "r"(b0), "r"(b1));
}
__device__ __forceinline__ void ldsm4(uint32_t addr, uint32_t* r) {
    asm volatile("ldmatrix.sync.aligned.m8n8.x4.shared.b16 {%0,%1,%2,%3}, [%4];"
                 : "=r"(r[0]), "=r"(r[1]), "=r"(r[2]), "=r"(r[3]) : "r"(addr));
}

// ==================== LoRA fold + bf16 hi/lo split ====================
__global__ void weff_kernel(const float* __restrict__ W, const float* __restrict__ A,
                            const float* __restrict__ Bm, int which) {
    int idx = blockIdx.x * 256 + threadIdx.x;
    int e = idx >> 10, k = idx & 1023;
    float acc = W[idx];
#pragma unroll
    for (int r = 0; r < 8; r++)
        acc = fmaf(2.0f * Bm[e * 8 + r], A[r * 1024 + k], acc);
    __nv_bfloat16 hi = __float2bfloat16_rn(acc);
    __nv_bfloat16 lo = __float2bfloat16_rn(acc - __bfloat162float(hi));
    g_whi[which][idx] = hi;
    g_wlo[which][idx] = lo;
}

// ==================== fp32 -> bf16 hi/lo conversion (x or attn) ====================
__global__ void cvt_kernel(const float* __restrict__ xsrc, int sel) {
    const float* src = sel ? g_attn : xsrc;
    __nv_bfloat16* hi = sel ? g_ahi : g_xhi;
    __nv_bfloat16* lo = sel ? g_alo : g_xlo;
    int i = blockIdx.x * 256 + threadIdx.x;
    float4 v = ((const float4*)src)[i];
    __nv_bfloat16 hx = __float2bfloat16_rn(v.x), hy = __float2bfloat16_rn(v.y);
    __nv_bfloat16 hz = __float2bfloat16_rn(v.z), hw = __float2bfloat16_rn(v.w);
    __nv_bfloat16 lx = __float2bfloat16_rn(v.x - __bfloat162float(hx));
    __nv_bfloat16 ly = __float2bfloat16_rn(v.y - __bfloat162float(hy));
    __nv_bfloat16 lz = __float2bfloat16_rn(v.z - __bfloat162float(hz));
    __nv_bfloat16 lw = __float2bfloat16_rn(v.w - __bfloat162float(hw));
    __nv_bfloat162* hp = (__nv_bfloat162*)hi + 2 * i;
    __nv_bfloat162* lp = (__nv_bfloat162*)lo + 2 * i;
    hp[0] = __halves2bfloat162(hx, hy); hp[1] = __halves2bfloat162(hz, hw);
    lp[0] = __halves2bfloat162(lx, ly); lp[1] = __halves2bfloat162(lz, lw);
}

// ==================== stable argsort (bitonic on (bucket<<12)|pos) ====================
__global__ void sort_kernel(const int* __restrict__ wb0, const int* __restrict__ wb1,
                            const int* __restrict__ wb2) {
    int batch = blockIdx.x, level = blockIdx.y;
    const int* wb = (level == 0) ? wb0 : (level == 1) ? wb1 : wb2;
    __shared__ unsigned key[N_];
    int tid = threadIdx.x;
    for (int i = tid; i < N_; i += 1024)
        key[i] = ((unsigned)wb[batch * N_ + i] << 12) | (unsigned)i;
    __syncthreads();
    for (int k = 2; k <= N_; k <<= 1) {
        for (int j = k >> 1; j > 0; j >>= 1) {
            for (int t = tid; t < N_; t += 1024) {
                int ixj = t ^ j;
                if (ixj > t) {
                    unsigned a = key[t], b = key[ixj];
                    bool up = ((t & k) == 0);
                    if ((a > b) == up) { key[t] = b; key[ixj] = a; }
                }
            }
            __syncthreads();
        }
    }
    for (int i = tid; i < N_; i += 1024)
        g_sidx[level][batch][i] = (int)(key[i] & 0xFFFu);
}

// ==================== HMMA bf16-split GEMM ====================
// CTA 128x128, K-chunk 64; 512 threads, warp grid 4x4 (32x32 warp tiles), ldmatrix loads.
static constexpr int TILEB = 128 * 128;
static constexpr int BUFB  = 4 * TILEB;                 // Ahi|Alo|Bhi|Blo = 64KB
static constexpr int GEMM_SMEM = 2 * BUFB;              // 128KB double-buffered

__global__ __launch_bounds__(512, 1) void gemm_tc(int qkv_mode,
                                                  const float* __restrict__ bias0,
                                                  const float* __restrict__ bias1,
                                                  const float* __restrict__ bias2,
                                                  float* __restrict__ out_ext) {
    extern __shared__ __align__(16) char dsm[];
    int z = blockIdx.z;
    const __nv_bfloat16 *Ahi, *Alo, *Bhi, *Blo;
    const float* bias;
    float* out;
    if (qkv_mode) {
        Ahi = g_xhi; Alo = g_xlo;
        Bhi = g_whi[z]; Blo = g_wlo[z];
        out = (z == 0) ? g_q : (z == 1) ? g_k : g_v;
        bias = (z == 0) ? bias0 : (z == 1) ? bias1 : bias2;
    } else {
        Ahi = g_ahi; Alo = g_alo;
        Bhi = g_whi[3]; Blo = g_wlo[3];
        out = out_ext; bias = bias0;
    }

    int tid = threadIdx.x;
    int wid = tid >> 5, lane = tid & 31;
    int g = lane >> 2, t = lane & 3;
    int wm = wid >> 2, wn = wid & 3;                    // 4x4 warp grid
    int m0 = blockIdx.x * 128, n0 = blockIdx.y * 128;

    uint32_t sbase = smem_u32(dsm);
    const __nv_bfloat16* srcs[4] = {
        Ahi + (size_t)m0 * E_, Alo + (size_t)m0 * E_,
        Bhi + (size_t)n0 * E_, Blo + (size_t)n0 * E_ };

    // loader: 512 threads = 4 tiles x 128 rows; 8x cp16 per thread per chunk
    int ltgt = tid >> 7, lrow = tid & 127;
    uint32_t lswz = (uint32_t)(lrow & 7) << 4;
    const __nv_bfloat16* lsrc = srcs[ltgt] + (size_t)lrow * E_;
    auto load_chunk = [&](int b, int kc) {
        uint32_t tb = sbase + b * BUFB + ltgt * TILEB + lrow * 128;
        const __nv_bfloat16* s = lsrc + kc * 64;
#pragma unroll
        for (int j = 0; j < 8; j++)
            cp16(tb + (((uint32_t)(j * 16)) ^ lswz), s + j * 8);
        CP_COMMIT();
    };

    // ldmatrix per-lane row/col roles
    int lane7 = lane & 7, st = lane >> 3;
    int arow = wm * 32 + (st & 1) * 8 + lane7;          // + mi*16
    uint32_t acolst = (uint32_t)((st >> 1) * 16);       // + ko*2
    int brow = wn * 32 + (st >> 1) * 8 + lane7;         // + nb*16
    uint32_t bcolst = (uint32_t)((st & 1) * 16);        // + ko*2

    float acc[2][4][4];
#pragma unroll
    for (int i = 0; i < 2; i++)
#pragma unroll
        for (int j = 0; j < 4; j++)
#pragma unroll
            for (int q = 0; q < 4; q++) acc[i][j][q] = 0.f;

    load_chunk(0, 0);

    for (int kc = 0; kc < 16; kc++) {
        int b = kc & 1;
        if (kc + 1 < 16) { load_chunk(b ^ 1, kc + 1); CP_WAIT(1); }
        else             { CP_WAIT(0); }
        __syncthreads();

        uint32_t tA  = sbase + b * BUFB;
        uint32_t tAl = tA + TILEB;
        uint32_t tB  = tA + 2 * TILEB;
        uint32_t tBl = tA + 3 * TILEB;

#pragma unroll
        for (int ks = 0; ks < 4; ks++) {
            uint32_t ko2 = (uint32_t)(ks * 32);
            uint32_t ah[2][4], al[2][4], bh[2][4], bl[2][4];
#pragma unroll
            for (int mi = 0; mi < 2; mi++) {
                int row = arow + mi * 16;
                uint32_t off = (uint32_t)(row * 128) + ((ko2 + acolst) ^ ((uint32_t)(row & 7) << 4));
                ldsm4(tA + off, ah[mi]);
                ldsm4(tAl + off, al[mi]);
            }
#pragma unroll
            for (int nb = 0; nb < 2; nb++) {
                int row = brow + nb * 16;
                uint32_t off = (uint32_t)(row * 128) + ((ko2 + bcolst) ^ ((uint32_t)(row & 7) << 4));
                ldsm4(tB + off, bh[nb]);
                ldsm4(tBl + off, bl[nb]);
            }
#pragma unroll
            for (int mi = 0; mi < 2; mi++)
#pragma unroll
                for (int ni = 0; ni < 4; ni++) {
                    int nb = ni >> 1, hf = (ni & 1) * 2;
                    mma16816(acc[mi][ni], ah[mi], bh[nb][hf], bh[nb][hf + 1]);
                    mma16816(acc[mi][ni], ah[mi], bl[nb][hf], bl[nb][hf + 1]);
                    mma16816(acc[mi][ni], al[mi], bh[nb][hf], bh[nb][hf + 1]);
                }
        }
        __syncthreads();
    }

    // epilogue
#pragma unroll
    for (int mi = 0; mi < 2; mi++) {
        int r0 = m0 + wm * 32 + mi * 16 + g;
#pragma unroll
        for (int ni = 0; ni < 4; ni++) {
            int col = n0 + wn * 32 + ni * 8 + 2 * t;
            float bx = bias[col], by = bias[col + 1];
            float2 v0 = { acc[mi][ni][0] + bx, acc[mi][ni][1] + by };
            float2 v1 = { acc[mi][ni][2] + bx, acc[mi][ni][3] + by };
            *(float2*)(out + (size_t)r0 * E_ + col) = v0;
            *(float2*)(out + (size_t)(r0 + 8) * E_ + col) = v1;
        }
    }
}

// ==================== chunked attention (scalar fp32, known-good) ====================
template <int C, int G, bool FIRST>
__global__ __launch_bounds__(256) void attn_kernel(int level) {
    constexpr int TK = 64;
    __shared__ float Ks[TK][HD_];
    __shared__ float Vs[TK][HD_];
    int bh = blockIdx.x;
    int batch = bh >> 4, h = bh & 15;
    int c0 = blockIdx.y * G;
    const int* sidx = &g_sidx[level][batch][0];
    int tid = threadIdx.x;
    int g = tid / C, li = tid % C;
    int chunk = c0 + g;
    int pq = chunk * C + li;
    int qtok = sidx[pq];
    size_t rowbase = ((size_t)(batch * N_ + qtok)) * E_ + h * HD_;
    const float* qrow = g_q + rowbase;

    float q[HD_], o[HD_];
#pragma unroll
    for (int d = 0; d < HD_; d += 4) {
        float4 qv = *(const float4*)(qrow + d);
        q[d] = qv.x; q[d + 1] = qv.y; q[d + 2] = qv.z; q[d + 3] = qv.w;
        o[d] = 0.f; o[d + 1] = 0.f; o[d + 2] = 0.f; o[d + 3] = 0.f;
    }
    float mmax = -1e30f, ssum = 0.f;

    int lo = (chunk == 0) ? 0 : (chunk - 1) * C;
    int hi = (chunk + 1) * C;
    int ulo = (c0 == 0) ? 0 : (c0 - 1) * C;
    int uhi = (c0 + G) * C;

    int r = tid >> 2, part = tid & 3;
    for (int t0 = ulo; t0 < uhi; t0 += TK) {
        int tn = min(TK, uhi - t0);
        if (r < tn) {
            int ktok = sidx[t0 + r];
            size_t kb = ((size_t)(batch * N_ + ktok)) * E_ + h * HD_;
            const float4* ksrc = (const float4*)(g_k + kb) + part * 4;
            const float4* vsrc = (const float4*)(g_v + kb) + part * 4;
            float4* kd = (float4*)&Ks[r][part * 16];
            float4* vd = (float4*)&Vs[r][part * 16];
#pragma unroll
            for (int u = 0; u < 4; u++) { kd[u] = ksrc[u]; vd[u] = vsrc[u]; }
        }
        __syncthreads();

        int jlo = max(lo, t0), jhi = min(hi, t0 + tn);
        for (int p = jlo; p < jhi; p++) {
            int jj = p - t0;
            float s0 = 0.f, s1 = 0.f, s2 = 0.f, s3 = 0.f;
#pragma unroll
            for (int d = 0; d < HD_; d += 4) {
                float4 kv = *(const float4*)&Ks[jj][d];
                s0 = fmaf(q[d],     kv.x, s0);
                s1 = fmaf(q[d + 1], kv.y, s1);
                s2 = fmaf(q[d + 2], kv.z, s2);
                s3 = fmaf(q[d + 3], kv.w, s3);
            }
            float sc = ((s0 + s1) + (s2 + s3)) * 0.125f;
            if (sc > mmax) {
                float corr = __expf(mmax - sc);
                ssum *= corr;
#pragma unroll
                for (int d = 0; d < HD_; d++) o[d] *= corr;
                mmax = sc;
            }
            float pw = __expf(sc - mmax);
            ssum += pw;
#pragma unroll
            for (int d = 0; d < HD_; d += 4) {
                float4 vv = *(const float4*)&Vs[jj][d];
                o[d]     = fmaf(pw, vv.x, o[d]);
                o[d + 1] = fmaf(pw, vv.y, o[d + 1]);
                o[d + 2] = fmaf(pw, vv.z, o[d + 2]);
                o[d + 3] = fmaf(pw, vv.w, o[d + 3]);
            }
        }
        __syncthreads();
    }

    float inv = 1.f / (3.f * ssum);
    float* dst = g_attn + rowbase;
#pragma unroll
    for (int d = 0; d < HD_; d++) {
        float v = o[d] * inv;
        if (FIRST) dst[d] = v; else dst[d] += v;
    }
}

// ==================== launch ====================
extern "C" void kernel_launch(void* const* d_in, const int* in_sizes, int n_in,
                              void* d_out, int out_size) {
    (void)in_sizes; (void)n_in; (void)out_size;
    const float* x   = (const float*)d_in[0];
    const int*   wbc = (const int*)d_in[1];
    const int*   wbm = (const int*)d_in[2];
    const int*   wbf = (const int*)d_in[3];
    const float* Wp[4] = { (const float*)d_in[4],  (const float*)d_in[8],
                           (const float*)d_in[12], (const float*)d_in[16] };
    const float* bp[4] = { (const float*)d_in[5],  (const float*)d_in[9],
                           (const float*)d_in[13], (const float*)d_in[17] };
    const float* Ap[4] = { (const float*)d_in[6],  (const float*)d_in[10],
                           (const float*)d_in[14], (const float*)d_in[18] };
    const float* Lp[4] = { (const float*)d_in[7],  (const float*)d_in[11],
                           (const float*)d_in[15], (const float*)d_in[19] };
    float* out = (float*)d_out;

    cudaFuncSetAttribute(gemm_tc, cudaFuncAttributeMaxDynamicSharedMemorySize, GEMM_SMEM);

    // 1) fold LoRA + split weights to bf16 hi/lo
    for (int p = 0; p < 4; p++)
        weff_kernel<<<(E_ * E_) / 256, 256>>>(Wp[p], Ap[p], Lp[p], p);

    // 2) split x to bf16 hi/lo
    cvt_kernel<<<(M_ * E_ / 4) / 256, 256>>>(x, 0);

    // 3) stable argsort per (batch, level)
    sort_kernel<<<dim3(B_, 3), 1024>>>(wbc, wbm, wbf);

    // 4) fused q,k,v projections (tensor cores, ldmatrix)
    gemm_tc<<<dim3(M_ / 128, E_ / 128, 3), 512, GEMM_SMEM>>>(1, bp[0], bp[1], bp[2], nullptr);

    // 5) three-level chunked attention
    attn_kernel<256, 1,  true ><<<dim3(BH_, 16), 256>>>(0);
    attn_kernel<64,  4,  false><<<dim3(BH_, 16), 256>>>(1);
    attn_kernel<16,  16, false><<<dim3(BH_, 16), 256>>>(2);

    // 6) split attention output to bf16 hi/lo
    cvt_kernel<<<(M_ * E_ / 4) / 256, 256>>>(nullptr, 1);

    // 7) output projection
    gemm_tc<<<dim3(M_ / 128, E_ / 128, 1), 512, GEMM_SMEM>>>(0, bp[3], nullptr, nullptr, out);
}

// round 5
// speedup vs baseline: 1.2114x; 1.2114x over previous
#include <cuda_runtime.h>
#include <cuda_bf16.h>
#include <math.h>
#include <stdint.h>

#define B_   2
#define N_   4096
#define E_   1024
#define H_   16
#define HD_  64
#define BH_  32
#define M_   8192

// ==================== device scratch ====================
__device__ __align__(16) __nv_bfloat16 g_whi[4][E_ * E_];
__device__ __align__(16) __nv_bfloat16 g_wlo[4][E_ * E_];
__device__ __align__(16) __nv_bfloat16 g_xhi[M_ * E_];
__device__ __align__(16) __nv_bfloat16 g_xlo[M_ * E_];
__device__ __align__(16) __nv_bfloat16 g_ahi[M_ * E_];
__device__ __align__(16) __nv_bfloat16 g_alo[M_ * E_];
__device__ float g_q[M_ * E_];
__device__ float g_k[M_ * E_];
__device__ float g_v[M_ * E_];
__device__ float g_attn[M_ * E_];
__device__ int   g_sidx[3][B_][N_];

// ==================== helpers ====================
__device__ __forceinline__ uint32_t smem_u32(const void* p) {
    uint32_t a;
    asm("{ .reg .u64 t; cvta.to.shared.u64 t, %1; cvt.u32.u64 %0, t; }" : "=r"(a) : "l"(p));
    return a;
}
__device__ __forceinline__ void cp16(uint32_t dst, const void* src) {
    asm volatile("cp.async.cg.shared.global [%0], [%1], 16;" :: "r"(dst), "l"(src));
}
#define CP_COMMIT() asm volatile("cp.async.commit_group;" ::: "memory")
#define CP_WAIT(n)  asm volatile("cp.async.wait_group %0;" :: "n"(n) : "memory")

__device__ __forceinline__ void mma16816(float* c, const uint32_t* a, uint32_t b0, uint32_t b1) {
    asm volatile(
        "mma.sync.aligned.m16n8k16.row.col.f32.bf16.bf16.f32 "
        "{%0,%1,%2,%3}, {%4,%5,%6,%7}, {%8,%9}, {%0,%1,%2,%3};"
        : "+f"(c[0]), "+f"(c[1]), "+f"(c[2]), "+f"(c[3])
        : "r"(a[0]), "r"(a[1]), "r"(a[2]), "r"(a[3]), "r"(b0), "r"(b1));
}
__device__ __forceinline__ void ldsm4(uint32_t addr, uint32_t* r) {
    asm volatile("ldmatrix.sync.aligned.m8n8.x4.shared.b16 {%0,%1,%2,%3}, [%4];"
                 : "=r"(r[0]), "=r"(r[1]), "=r"(r[2]), "=r"(r[3]) : "r"(addr));
}

// ==================== LoRA fold + bf16 hi/lo split ====================
__global__ void weff_kernel(const float* __restrict__ W, const float* __restrict__ A,
                            const float* __restrict__ Bm, int which) {
    int idx = blockIdx.x * 256 + threadIdx.x;
    int e = idx >> 10, k = idx & 1023;
    float acc = W[idx];
#pragma unroll
    for (int r = 0; r < 8; r++)
        acc = fmaf(2.0f * Bm[e * 8 + r], A[r * 1024 + k], acc);
    __nv_bfloat16 hi = __float2bfloat16_rn(acc);
    __nv_bfloat16 lo = __float2bfloat16_rn(acc - __bfloat162float(hi));
    g_whi[which][idx] = hi;
    g_wlo[which][idx] = lo;
}

// ==================== fp32 -> bf16 hi/lo conversion (x or attn) ====================
__global__ void cvt_kernel(const float* __restrict__ xsrc, int sel) {
    const float* src = sel ? g_attn : xsrc;
    __nv_bfloat16* hi = sel ? g_ahi : g_xhi;
    __nv_bfloat16* lo = sel ? g_alo : g_xlo;
    int i = blockIdx.x * 256 + threadIdx.x;
    float4 v = ((const float4*)src)[i];
    __nv_bfloat16 hx = __float2bfloat16_rn(v.x), hy = __float2bfloat16_rn(v.y);
    __nv_bfloat16 hz = __float2bfloat16_rn(v.z), hw = __float2bfloat16_rn(v.w);
    __nv_bfloat16 lx = __float2bfloat16_rn(v.x - __bfloat162float(hx));
    __nv_bfloat16 ly = __float2bfloat16_rn(v.y - __bfloat162float(hy));
    __nv_bfloat16 lz = __float2bfloat16_rn(v.z - __bfloat162float(hz));
    __nv_bfloat16 lw = __float2bfloat16_rn(v.w - __bfloat162float(hw));
    __nv_bfloat162* hp = (__nv_bfloat162*)hi + 2 * i;
    __nv_bfloat162* lp = (__nv_bfloat162*)lo + 2 * i;
    hp[0] = __halves2bfloat162(hx, hy); hp[1] = __halves2bfloat162(hz, hw);
    lp[0] = __halves2bfloat162(lx, ly); lp[1] = __halves2bfloat162(lz, lw);
}

// ==================== stable argsort (bitonic on (bucket<<12)|pos) ====================
__global__ void sort_kernel(const int* __restrict__ wb0, const int* __restrict__ wb1,
                            const int* __restrict__ wb2) {
    int batch = blockIdx.x, level = blockIdx.y;
    const int* wb = (level == 0) ? wb0 : (level == 1) ? wb1 : wb2;
    __shared__ unsigned key[N_];
    int tid = threadIdx.x;
    for (int i = tid; i < N_; i += 1024)
        key[i] = ((unsigned)wb[batch * N_ + i] << 12) | (unsigned)i;
    __syncthreads();
    for (int k = 2; k <= N_; k <<= 1) {
        for (int j = k >> 1; j > 0; j >>= 1) {
            for (int t = tid; t < N_; t += 1024) {
                int ixj = t ^ j;
                if (ixj > t) {
                    unsigned a = key[t], b = key[ixj];
                    bool up = ((t & k) == 0);
                    if ((a > b) == up) { key[t] = b; key[ixj] = a; }
                }
            }
            __syncthreads();
        }
    }
    for (int i = tid; i < N_; i += 1024)
        g_sidx[level][batch][i] = (int)(key[i] & 0xFFFu);
}

// ==================== HMMA bf16-split GEMM ====================
// CTA 128x128, K-chunk 64; 512 threads, warp grid 4x4 (32x32 warp tiles), ldmatrix loads.
static constexpr int TILEB = 128 * 128;
static constexpr int BUFB  = 4 * TILEB;                 // Ahi|Alo|Bhi|Blo = 64KB
static constexpr int GEMM_SMEM = 2 * BUFB;              // 128KB double-buffered

__global__ __launch_bounds__(512, 1) void gemm_tc(int qkv_mode,
                                                  const float* __restrict__ bias0,
                                                  const float* __restrict__ bias1,
                                                  const float* __restrict__ bias2,
                                                  float* __restrict__ out_ext) {
    extern __shared__ __align__(16) char dsm[];
    int z = blockIdx.z;
    const __nv_bfloat16 *Ahi, *Alo, *Bhi, *Blo;
    const float* bias;
    float* out;
    if (qkv_mode) {
        Ahi = g_xhi; Alo = g_xlo;
        Bhi = g_whi[z]; Blo = g_wlo[z];
        out = (z == 0) ? g_q : (z == 1) ? g_k : g_v;
        bias = (z == 0) ? bias0 : (z == 1) ? bias1 : bias2;
    } else {
        Ahi = g_ahi; Alo = g_alo;
        Bhi = g_whi[3]; Blo = g_wlo[3];
        out = out_ext; bias = bias0;
    }

    int tid = threadIdx.x;
    int wid = tid >> 5, lane = tid & 31;
    int g = lane >> 2, t = lane & 3;
    int wm = wid >> 2, wn = wid & 3;                    // 4x4 warp grid
    int m0 = blockIdx.x * 128, n0 = blockIdx.y * 128;

    uint32_t sbase = smem_u32(dsm);
    const __nv_bfloat16* srcs[4] = {
        Ahi + (size_t)m0 * E_, Alo + (size_t)m0 * E_,
        Bhi + (size_t)n0 * E_, Blo + (size_t)n0 * E_ };

    // loader: COALESCED — 8 consecutive threads fetch 8 consecutive 16B chunks of one row.
    // tid -> c = tid&7 (16B column chunk), r6 = (tid>>3)&63 (row within 64-row half).
    int lc = tid & 7, r6 = (tid >> 3) & 63;
    uint32_t cbyte = (uint32_t)(lc * 16);
    auto load_chunk = [&](int b, int kc) {
#pragma unroll
        for (int tgt = 0; tgt < 4; tgt++) {
            uint32_t tb = sbase + b * BUFB + tgt * TILEB;
            const __nv_bfloat16* s = srcs[tgt] + kc * 64 + lc * 8;
#pragma unroll
            for (int p = 0; p < 2; p++) {
                int row = p * 64 + r6;
                cp16(tb + row * 128 + (cbyte ^ ((uint32_t)(row & 7) << 4)),
                     s + (size_t)row * E_);
            }
        }
        CP_COMMIT();
    };

    // ldmatrix per-lane row/col roles
    int lane7 = lane & 7, st = lane >> 3;
    int arow = wm * 32 + (st & 1) * 8 + lane7;          // + mi*16
    uint32_t acolst = (uint32_t)((st >> 1) * 16);       // byte offset within k16 slice
    int brow = wn * 32 + (st >> 1) * 8 + lane7;         // + nb*16
    uint32_t bcolst = (uint32_t)((st & 1) * 16);

    float acc[2][4][4];
#pragma unroll
    for (int i = 0; i < 2; i++)
#pragma unroll
        for (int j = 0; j < 4; j++)
#pragma unroll
            for (int q = 0; q < 4; q++) acc[i][j][q] = 0.f;

    load_chunk(0, 0);

    for (int kc = 0; kc < 16; kc++) {
        int b = kc & 1;
        if (kc + 1 < 16) { load_chunk(b ^ 1, kc + 1); CP_WAIT(1); }
        else             { CP_WAIT(0); }
        __syncthreads();

        uint32_t tA  = sbase + b * BUFB;
        uint32_t tAl = tA + TILEB;
        uint32_t tB  = tA + 2 * TILEB;
        uint32_t tBl = tA + 3 * TILEB;

#pragma unroll
        for (int ks = 0; ks < 4; ks++) {
            uint32_t ko2 = (uint32_t)(ks * 32);
            uint32_t ah[2][4], al[2][4], bh[2][4], bl[2][4];
#pragma unroll
            for (int mi = 0; mi < 2; mi++) {
                int row = arow + mi * 16;
                uint32_t off = (uint32_t)(row * 128) + ((ko2 + acolst) ^ ((uint32_t)(row & 7) << 4));
                ldsm4(tA + off, ah[mi]);
                ldsm4(tAl + off, al[mi]);
            }
#pragma unroll
            for (int nb = 0; nb < 2; nb++) {
                int row = brow + nb * 16;
                uint32_t off = (uint32_t)(row * 128) + ((ko2 + bcolst) ^ ((uint32_t)(row & 7) << 4));
                ldsm4(tB + off, bh[nb]);
                ldsm4(tBl + off, bl[nb]);
            }
#pragma unroll
            for (int mi = 0; mi < 2; mi++)
#pragma unroll
                for (int ni = 0; ni < 4; ni++) {
                    int nb = ni >> 1, hf = (ni & 1) * 2;
                    mma16816(acc[mi][ni], ah[mi], bh[nb][hf], bh[nb][hf + 1]);
                    mma16816(acc[mi][ni], ah[mi], bl[nb][hf], bl[nb][hf + 1]);
                    mma16816(acc[mi][ni], al[mi], bh[nb][hf], bh[nb][hf + 1]);
                }
        }
        __syncthreads();
    }

    // epilogue
#pragma unroll
    for (int mi = 0; mi < 2; mi++) {
        int r0 = m0 + wm * 32 + mi * 16 + g;
#pragma unroll
        for (int ni = 0; ni < 4; ni++) {
            int col = n0 + wn * 32 + ni * 8 + 2 * t;
            float bx = bias[col], by = bias[col + 1];
            float2 v0 = { acc[mi][ni][0] + bx, acc[mi][ni][1] + by };
            float2 v1 = { acc[mi][ni][2] + bx, acc[mi][ni][3] + by };
            *(float2*)(out + (size_t)r0 * E_ + col) = v0;
            *(float2*)(out + (size_t)(r0 + 8) * E_ + col) = v1;
        }
    }
}

// ==================== chunked attention (scalar fp32, known-good) ====================
template <int C, int G, bool FIRST>
__global__ __launch_bounds__(256) void attn_kernel(int level) {
    constexpr int TK = 64;
    __shared__ float Ks[TK][HD_];
    __shared__ float Vs[TK][HD_];
    int bh = blockIdx.x;
    int batch = bh >> 4, h = bh & 15;
    int c0 = blockIdx.y * G;
    const int* sidx = &g_sidx[level][batch][0];
    int tid = threadIdx.x;
    int g = tid / C, li = tid % C;
    int chunk = c0 + g;
    int pq = chunk * C + li;
    int qtok = sidx[pq];
    size_t rowbase = ((size_t)(batch * N_ + qtok)) * E_ + h * HD_;
    const float* qrow = g_q + rowbase;

    float q[HD_], o[HD_];
#pragma unroll
    for (int d = 0; d < HD_; d += 4) {
        float4 qv = *(const float4*)(qrow + d);
        q[d] = qv.x; q[d + 1] = qv.y; q[d + 2] = qv.z; q[d + 3] = qv.w;
        o[d] = 0.f; o[d + 1] = 0.f; o[d + 2] = 0.f; o[d + 3] = 0.f;
    }
    float mmax = -1e30f, ssum = 0.f;

    int lo = (chunk == 0) ? 0 : (chunk - 1) * C;
    int hi = (chunk + 1) * C;
    int ulo = (c0 == 0) ? 0 : (c0 - 1) * C;
    int uhi = (c0 + G) * C;

    int r = tid >> 2, part = tid & 3;
    for (int t0 = ulo; t0 < uhi; t0 += TK) {
        int tn = min(TK, uhi - t0);
        if (r < tn) {
            int ktok = sidx[t0 + r];
            size_t kb = ((size_t)(batch * N_ + ktok)) * E_ + h * HD_;
            const float4* ksrc = (const float4*)(g_k + kb) + part * 4;
            const float4* vsrc = (const float4*)(g_v + kb) + part * 4;
            float4* kd = (float4*)&Ks[r][part * 16];
            float4* vd = (float4*)&Vs[r][part * 16];
#pragma unroll
            for (int u = 0; u < 4; u++) { kd[u] = ksrc[u]; vd[u] = vsrc[u]; }
        }
        __syncthreads();

        int jlo = max(lo, t0), jhi = min(hi, t0 + tn);
        for (int p = jlo; p < jhi; p++) {
            int jj = p - t0;
            float s0 = 0.f, s1 = 0.f, s2 = 0.f, s3 = 0.f;
#pragma unroll
            for (int d = 0; d < HD_; d += 4) {
                float4 kv = *(const float4*)&Ks[jj][d];
                s0 = fmaf(q[d],     kv.x, s0);
                s1 = fmaf(q[d + 1], kv.y, s1);
                s2 = fmaf(q[d + 2], kv.z, s2);
                s3 = fmaf(q[d + 3], kv.w, s3);
            }
            float sc = ((s0 + s1) + (s2 + s3)) * 0.125f;
            if (sc > mmax) {
                float corr = __expf(mmax - sc);
                ssum *= corr;
#pragma unroll
                for (int d = 0; d < HD_; d++) o[d] *= corr;
                mmax = sc;
            }
            float pw = __expf(sc - mmax);
            ssum += pw;
#pragma unroll
            for (int d = 0; d < HD_; d += 4) {
                float4 vv = *(const float4*)&Vs[jj][d];
                o[d]     = fmaf(pw, vv.x, o[d]);
                o[d + 1] = fmaf(pw, vv.y, o[d + 1]);
                o[d + 2] = fmaf(pw, vv.z, o[d + 2]);
                o[d + 3] = fmaf(pw, vv.w, o[d + 3]);
            }
        }
        __syncthreads();
    }

    float inv = 1.f / (3.f * ssum);
    float* dst = g_attn + rowbase;
#pragma unroll
    for (int d = 0; d < HD_; d++) {
        float v = o[d] * inv;
        if (FIRST) dst[d] = v; else dst[d] += v;
    }
}

// ==================== launch ====================
extern "C" void kernel_launch(void* const* d_in, const int* in_sizes, int n_in,
                              void* d_out, int out_size) {
    (void)in_sizes; (void)n_in; (void)out_size;
    const float* x   = (const float*)d_in[0];
    const int*   wbc = (const int*)d_in[1];
    const int*   wbm = (const int*)d_in[2];
    const int*   wbf = (const int*)d_in[3];
    const float* Wp[4] = { (const float*)d_in[4],  (const float*)d_in[8],
                           (const float*)d_in[12], (const float*)d_in[16] };
    const float* bp[4] = { (const float*)d_in[5],  (const float*)d_in[9],
                           (const float*)d_in[13], (const float*)d_in[17] };
    const float* Ap[4] = { (const float*)d_in[6],  (const float*)d_in[10],
                           (const float*)d_in[14], (const float*)d_in[18] };
    const float* Lp[4] = { (const float*)d_in[7],  (const float*)d_in[11],
                           (const float*)d_in[15], (const float*)d_in[19] };
    float* out = (float*)d_out;

    cudaFuncSetAttribute(gemm_tc, cudaFuncAttributeMaxDynamicSharedMemorySize, GEMM_SMEM);

    // 1) fold LoRA + split weights to bf16 hi/lo
    for (int p = 0; p < 4; p++)
        weff_kernel<<<(E_ * E_) / 256, 256>>>(Wp[p], Ap[p], Lp[p], p);

    // 2) split x to bf16 hi/lo
    cvt_kernel<<<(M_ * E_ / 4) / 256, 256>>>(x, 0);

    // 3) stable argsort per (batch, level)
    sort_kernel<<<dim3(B_, 3), 1024>>>(wbc, wbm, wbf);

    // 4) fused q,k,v projections (tensor cores, ldmatrix, coalesced cp.async)
    gemm_tc<<<dim3(M_ / 128, E_ / 128, 3), 512, GEMM_SMEM>>>(1, bp[0], bp[1], bp[2], nullptr);

    // 5) three-level chunked attention
    attn_kernel<256, 1,  true ><<<dim3(BH_, 16), 256>>>(0);
    attn_kernel<64,  4,  false><<<dim3(BH_, 16), 256>>>(1);
    attn_kernel<16,  16, false><<<dim3(BH_, 16), 256>>>(2);

    // 6) split attention output to bf16 hi/lo
    cvt_kernel<<<(M_ * E_ / 4) / 256, 256>>>(nullptr, 1);

    // 7) output projection
    gemm_tc<<<dim3(M_ / 128, E_ / 128, 1), 512, GEMM_SMEM>>>(0, bp[3], nullptr, nullptr, out);
}

// round 6
// speedup vs baseline: 1.2921x; 1.0666x over previous
#include <cuda_runtime.h>
#include <cuda_fp16.h>
#include <math.h>
#include <stdint.h>

#define B_   2
#define N_   4096
#define E_   1024
#define H_   16
#define HD_  64
#define BH_  32
#define M_   8192

typedef unsigned long long u64;

// ==================== device scratch ====================
__device__ __align__(16) __half g_whi[4][E_ * E_];
__device__ __align__(16) __half g_wlo[4][E_ * E_];
__device__ __align__(16) __half g_xhi[M_ * E_];     // fp16(x)
__device__ __align__(16) __half g_ahi[M_ * E_];     // fp16(attn)
__device__ float g_q[M_ * E_];
__device__ float g_k[M_ * E_];
__device__ float g_v[M_ * E_];
__device__ float g_attn[M_ * E_];
__device__ int   g_sidx[3][B_][N_];

// ==================== helpers ====================
__device__ __forceinline__ uint32_t smem_u32(const void* p) {
    uint32_t a;
    asm("{ .reg .u64 t; cvta.to.shared.u64 t, %1; cvt.u32.u64 %0, t; }" : "=r"(a) : "l"(p));
    return a;
}
__device__ __forceinline__ void cp16(uint32_t dst, const void* src) {
    asm volatile("cp.async.cg.shared.global [%0], [%1], 16;" :: "r"(dst), "l"(src));
}
#define CP_COMMIT() asm volatile("cp.async.commit_group;" ::: "memory")
#define CP_WAIT(n)  asm volatile("cp.async.wait_group %0;" :: "n"(n) : "memory")

__device__ __forceinline__ void mma16816(float* c, const uint32_t* a, uint32_t b0, uint32_t b1) {
    asm volatile(
        "mma.sync.aligned.m16n8k16.row.col.f32.f16.f16.f32 "
        "{%0,%1,%2,%3}, {%4,%5,%6,%7}, {%8,%9}, {%0,%1,%2,%3};"
        : "+f"(c[0]), "+f"(c[1]), "+f"(c[2]), "+f"(c[3])
        : "r"(a[0]), "r"(a[1]), "r"(a[2]), "r"(a[3]), "r"(b0), "r"(b1));
}
__device__ __forceinline__ void ldsm4(uint32_t addr, uint32_t* r) {
    asm volatile("ldmatrix.sync.aligned.m8n8.x4.shared.b16 {%0,%1,%2,%3}, [%4];"
                 : "=r"(r[0]), "=r"(r[1]), "=r"(r[2]), "=r"(r[3]) : "r"(addr));
}

// packed f32x2 math (verified to pass ptxas on sm_103 in round-2 build)
__device__ __forceinline__ u64 ffma2(u64 a, u64 b, u64 c) {
    u64 d; asm("fma.rn.f32x2 %0, %1, %2, %3;" : "=l"(d) : "l"(a), "l"(b), "l"(c)); return d;
}
__device__ __forceinline__ u64 fmul2(u64 a, u64 b) {
    u64 d; asm("mul.rn.f32x2 %0, %1, %2;" : "=l"(d) : "l"(a), "l"(b)); return d;
}
__device__ __forceinline__ u64 pack2(float lo, float hi) {
    u64 r; asm("mov.b64 %0, {%1, %2};" : "=l"(r) : "f"(lo), "f"(hi)); return r;
}
__device__ __forceinline__ float2 unpk2(u64 a) {
    float2 f; asm("mov.b64 {%0, %1}, %2;" : "=f"(f.x), "=f"(f.y) : "l"(a)); return f;
}

// ==================== LoRA fold + fp16 hi/lo split (weights) ====================
__global__ void weff_kernel(const float* __restrict__ W, const float* __restrict__ A,
                            const float* __restrict__ Bm, int which) {
    int idx = blockIdx.x * 256 + threadIdx.x;
    int e = idx >> 10, k = idx & 1023;
    float acc = W[idx];
#pragma unroll
    for (int r = 0; r < 8; r++)
        acc = fmaf(2.0f * Bm[e * 8 + r], A[r * 1024 + k], acc);
    __half hi = __float2half_rn(acc);
    __half lo = __float2half_rn(acc - __half2float(hi));
    g_whi[which][idx] = hi;
    g_wlo[which][idx] = lo;
}

// ==================== fp32 -> fp16 conversion (x or attn; hi only) ====================
__global__ void cvt_kernel(const float* __restrict__ xsrc, int sel) {
    const float* src = sel ? g_attn : xsrc;
    __half* hi = sel ? g_ahi : g_xhi;
    int i = blockIdx.x * 256 + threadIdx.x;
    float4 v = ((const float4*)src)[i];
    __half2* hp = (__half2*)hi + 2 * i;
    hp[0] = __floats2half2_rn(v.x, v.y);
    hp[1] = __floats2half2_rn(v.z, v.w);
}

// ==================== stable argsort (bitonic on (bucket<<12)|pos) ====================
__global__ void sort_kernel(const int* __restrict__ wb0, const int* __restrict__ wb1,
                            const int* __restrict__ wb2) {
    int batch = blockIdx.x, level = blockIdx.y;
    const int* wb = (level == 0) ? wb0 : (level == 1) ? wb1 : wb2;
    __shared__ unsigned key[N_];
    int tid = threadIdx.x;
    for (int i = tid; i < N_; i += 1024)
        key[i] = ((unsigned)wb[batch * N_ + i] << 12) | (unsigned)i;
    __syncthreads();
    for (int k = 2; k <= N_; k <<= 1) {
        for (int j = k >> 1; j > 0; j >>= 1) {
            for (int t = tid; t < N_; t += 1024) {
                int ixj = t ^ j;
                if (ixj > t) {
                    unsigned a = key[t], b = key[ixj];
                    bool up = ((t & k) == 0);
                    if ((a > b) == up) { key[t] = b; key[ixj] = a; }
                }
            }
            __syncthreads();
        }
    }
    for (int i = tid; i < N_; i += 1024)
        g_sidx[level][batch][i] = (int)(key[i] & 0xFFFu);
}

// ==================== HMMA fp16 2-product GEMM ====================
// out = Ah @ (Wh + Wl)^T + bias.  CTA 128x128, K-chunk 64, 512 threads,
// 4x4 warp grid (32x32 warp tiles), ldmatrix loads, tiles: Ah | Bh | Bl.
static constexpr int TILEB = 128 * 128;                 // 16KB per tile
static constexpr int BUFB  = 3 * TILEB;                 // 48KB per buffer
static constexpr int GEMM_SMEM = 2 * BUFB;              // 96KB double-buffered

__global__ __launch_bounds__(512, 1) void gemm_tc(int qkv_mode,
                                                  const float* __restrict__ bias0,
                                                  const float* __restrict__ bias1,
                                                  const float* __restrict__ bias2,
                                                  float* __restrict__ out_ext) {
    extern __shared__ __align__(16) char dsm[];
    int z = blockIdx.z;
    const __half *Ah, *Bh, *Bl;
    const float* bias;
    float* out;
    if (qkv_mode) {
        Ah = g_xhi;
        Bh = g_whi[z]; Bl = g_wlo[z];
        out = (z == 0) ? g_q : (z == 1) ? g_k : g_v;
        bias = (z == 0) ? bias0 : (z == 1) ? bias1 : bias2;
    } else {
        Ah = g_ahi;
        Bh = g_whi[3]; Bl = g_wlo[3];
        out = out_ext; bias = bias0;
    }

    int tid = threadIdx.x;
    int wid = tid >> 5, lane = tid & 31;
    int g = lane >> 2, t = lane & 3;
    int wm = wid >> 2, wn = wid & 3;                    // 4x4 warp grid
    int m0 = blockIdx.x * 128, n0 = blockIdx.y * 128;

    uint32_t sbase = smem_u32(dsm);
    const __half* srcs[3] = {
        Ah + (size_t)m0 * E_, Bh + (size_t)n0 * E_, Bl + (size_t)n0 * E_ };

    // coalesced loader: 8 consecutive threads fetch 8 consecutive 16B chunks of one row
    int lc = tid & 7, r6 = (tid >> 3) & 63;
    uint32_t cbyte = (uint32_t)(lc * 16);
    auto load_chunk = [&](int b, int kc) {
#pragma unroll
        for (int tgt = 0; tgt < 3; tgt++) {
            uint32_t tb = sbase + b * BUFB + tgt * TILEB;
            const __half* s = srcs[tgt] + kc * 64 + lc * 8;
#pragma unroll
            for (int p = 0; p < 2; p++) {
                int row = p * 64 + r6;
                cp16(tb + row * 128 + (cbyte ^ ((uint32_t)(row & 7) << 4)),
                     s + (size_t)row * E_);
            }
        }
        CP_COMMIT();
    };

    // ldmatrix per-lane row/col roles
    int lane7 = lane & 7, st = lane >> 3;
    int arow = wm * 32 + (st & 1) * 8 + lane7;
    uint32_t acolst = (uint32_t)((st >> 1) * 16);
    int brow = wn * 32 + (st >> 1) * 8 + lane7;
    uint32_t bcolst = (uint32_t)((st & 1) * 16);

    float acc[2][4][4];
#pragma unroll
    for (int i = 0; i < 2; i++)
#pragma unroll
        for (int j = 0; j < 4; j++)
#pragma unroll
            for (int q = 0; q < 4; q++) acc[i][j][q] = 0.f;

    load_chunk(0, 0);

    for (int kc = 0; kc < 16; kc++) {
        int b = kc & 1;
        if (kc + 1 < 16) { load_chunk(b ^ 1, kc + 1); CP_WAIT(1); }
        else             { CP_WAIT(0); }
        __syncthreads();

        uint32_t tA  = sbase + b * BUFB;
        uint32_t tB  = tA + TILEB;
        uint32_t tBl = tA + 2 * TILEB;

#pragma unroll
        for (int ks = 0; ks < 4; ks++) {
            uint32_t ko2 = (uint32_t)(ks * 32);
            uint32_t ah[2][4], bh[2][4], bl[2][4];
#pragma unroll
            for (int mi = 0; mi < 2; mi++) {
                int row = arow + mi * 16;
                uint32_t off = (uint32_t)(row * 128) + ((ko2 + acolst) ^ ((uint32_t)(row & 7) << 4));
                ldsm4(tA + off, ah[mi]);
            }
#pragma unroll
            for (int nb = 0; nb < 2; nb++) {
                int row = brow + nb * 16;
                uint32_t off = (uint32_t)(row * 128) + ((ko2 + bcolst) ^ ((uint32_t)(row & 7) << 4));
                ldsm4(tB + off, bh[nb]);
                ldsm4(tBl + off, bl[nb]);
            }
#pragma unroll
            for (int mi = 0; mi < 2; mi++)
#pragma unroll
                for (int ni = 0; ni < 4; ni++) {
                    int nb = ni >> 1, hf = (ni & 1) * 2;
                    mma16816(acc[mi][ni], ah[mi], bh[nb][hf], bh[nb][hf + 1]);
                    mma16816(acc[mi][ni], ah[mi], bl[nb][hf], bl[nb][hf + 1]);
                }
        }
        __syncthreads();
    }

    // epilogue
#pragma unroll
    for (int mi = 0; mi < 2; mi++) {
        int r0 = m0 + wm * 32 + mi * 16 + g;
#pragma unroll
        for (int ni = 0; ni < 4; ni++) {
            int col = n0 + wn * 32 + ni * 8 + 2 * t;
            float bx = bias[col], by = bias[col + 1];
            float2 v0 = { acc[mi][ni][0] + bx, acc[mi][ni][1] + by };
            float2 v1 = { acc[mi][ni][2] + bx, acc[mi][ni][3] + by };
            *(float2*)(out + (size_t)r0 * E_ + col) = v0;
            *(float2*)(out + (size_t)(r0 + 8) * E_ + col) = v1;
        }
    }
}

// ==================== chunked attention (packed f32x2) ====================
template <int C, int G, bool FIRST>
__global__ __launch_bounds__(256) void attn_kernel(int level) {
    constexpr int TK = 64;
    __shared__ float Ks[TK][HD_];
    __shared__ float Vs[TK][HD_];
    int bh = blockIdx.x;
    int batch = bh >> 4, h = bh & 15;
    int c0 = blockIdx.y * G;
    const int* sidx = &g_sidx[level][batch][0];
    int tid = threadIdx.x;
    int g = tid / C, li = tid % C;
    int chunk = c0 + g;
    int pq = chunk * C + li;
    int qtok = sidx[pq];
    size_t rowbase = ((size_t)(batch * N_ + qtok)) * E_ + h * HD_;

    u64 q2[32], o2[32];
    const u64* q2g = (const u64*)(g_q + rowbase);
#pragma unroll
    for (int i = 0; i < 32; i++) { q2[i] = q2g[i]; o2[i] = 0ULL; }
    float mmax = -1e30f, ssum = 0.f;

    int lo = (chunk == 0) ? 0 : (chunk - 1) * C;
    int hi = (chunk + 1) * C;
    int ulo = (c0 == 0) ? 0 : (c0 - 1) * C;
    int uhi = (c0 + G) * C;

    int r = tid >> 2, part = tid & 3;
    for (int t0 = ulo; t0 < uhi; t0 += TK) {
        int tn = min(TK, uhi - t0);
        if (r < tn) {
            int ktok = sidx[t0 + r];
            size_t kb = ((size_t)(batch * N_ + ktok)) * E_ + h * HD_;
            const float4* ksrc = (const float4*)(g_k + kb) + part * 4;
            const float4* vsrc = (const float4*)(g_v + kb) + part * 4;
            float4* kd = (float4*)&Ks[r][part * 16];
            float4* vd = (float4*)&Vs[r][part * 16];
#pragma unroll
            for (int u = 0; u < 4; u++) { kd[u] = ksrc[u]; vd[u] = vsrc[u]; }
        }
        __syncthreads();

        int jlo = max(lo, t0), jhi = min(hi, t0 + tn);
        for (int p = jlo; p < jhi; p++) {
            int jj = p - t0;
            const u64* k2 = (const u64*)&Ks[jj][0];
            u64 a0 = 0ULL, a1 = 0ULL, a2 = 0ULL, a3 = 0ULL;
#pragma unroll
            for (int i = 0; i < 32; i += 4) {
                a0 = ffma2(q2[i],     k2[i],     a0);
                a1 = ffma2(q2[i + 1], k2[i + 1], a1);
                a2 = ffma2(q2[i + 2], k2[i + 2], a2);
                a3 = ffma2(q2[i + 3], k2[i + 3], a3);
            }
            float2 f0 = unpk2(a0), f1 = unpk2(a1), f2 = unpk2(a2), f3 = unpk2(a3);
            float sc = (((f0.x + f0.y) + (f1.x + f1.y)) + ((f2.x + f2.y) + (f3.x + f3.y))) * 0.125f;
            if (sc > mmax) {
                float corr = __expf(mmax - sc);
                ssum *= corr;
                u64 cp = pack2(corr, corr);
#pragma unroll
                for (int i = 0; i < 32; i++) o2[i] = fmul2(cp, o2[i]);
                mmax = sc;
            }
            float pw = __expf(sc - mmax);
            ssum += pw;
            u64 pp = pack2(pw, pw);
            const u64* v2 = (const u64*)&Vs[jj][0];
#pragma unroll
            for (int i = 0; i < 32; i++) o2[i] = ffma2(pp, v2[i], o2[i]);
        }
        __syncthreads();
    }

    float inv = 1.f / (3.f * ssum);
    float* dst = g_attn + rowbase;
#pragma unroll
    for (int i = 0; i < 32; i++) {
        float2 f = unpk2(o2[i]);
        if (FIRST) { dst[2 * i] = f.x * inv;  dst[2 * i + 1] = f.y * inv; }
        else       { dst[2 * i] += f.x * inv; dst[2 * i + 1] += f.y * inv; }
    }
}

// ==================== launch ====================
extern "C" void kernel_launch(void* const* d_in, const int* in_sizes, int n_in,
                              void* d_out, int out_size) {
    (void)in_sizes; (void)n_in; (void)out_size;
    const float* x   = (const float*)d_in[0];
    const int*   wbc = (const int*)d_in[1];
    const int*   wbm = (const int*)d_in[2];
    const int*   wbf = (const int*)d_in[3];
    const float* Wp[4] = { (const float*)d_in[4],  (const float*)d_in[8],
                           (const float*)d_in[12], (const float*)d_in[16] };
    const float* bp[4] = { (const float*)d_in[5],  (const float*)d_in[9],
                           (const float*)d_in[13], (const float*)d_in[17] };
    const float* Ap[4] = { (const float*)d_in[6],  (const float*)d_in[10],
                           (const float*)d_in[14], (const float*)d_in[18] };
    const float* Lp[4] = { (const float*)d_in[7],  (const float*)d_in[11],
                           (const float*)d_in[15], (const float*)d_in[19] };
    float* out = (float*)d_out;

    cudaFuncSetAttribute(gemm_tc, cudaFuncAttributeMaxDynamicSharedMemorySize, GEMM_SMEM);

    // 1) fold LoRA + split weights to fp16 hi/lo         (launches 1-4)
    for (int p = 0; p < 4; p++)
        weff_kernel<<<(E_ * E_) / 256, 256>>>(Wp[p], Ap[p], Lp[p], p);

    // 2) convert x to fp16                                (launch 5)
    cvt_kernel<<<(M_ * E_ / 4) / 256, 256>>>(x, 0);

    // 3) fused q,k,v projections                          (launch 6 — ncu -s5 target)
    gemm_tc<<<dim3(M_ / 128, E_ / 128, 3), 512, GEMM_SMEM>>>(1, bp[0], bp[1], bp[2], nullptr);

    // 4) stable argsort per (batch, level)
    sort_kernel<<<dim3(B_, 3), 1024>>>(wbc, wbm, wbf);

    // 5) three-level chunked attention (f32x2)
    attn_kernel<256, 1,  true ><<<dim3(BH_, 16), 256>>>(0);
    attn_kernel<64,  4,  false><<<dim3(BH_, 16), 256>>>(1);
    attn_kernel<16,  16, false><<<dim3(BH_, 16), 256>>>(2);

    // 6) convert attention output to fp16
    cvt_kernel<<<(M_ * E_ / 4) / 256, 256>>>(nullptr, 1);

    // 7) output projection
    gemm_tc<<<dim3(M_ / 128, E_ / 128, 1), 512, GEMM_SMEM>>>(0, bp[3], nullptr, nullptr, out);
}

// round 7
// speedup vs baseline: 3.9333x; 3.0442x over previous
#include <cuda_runtime.h>
#include <cuda_fp16.h>
#include <math.h>
#include <stdint.h>

#define B_   2
#define N_   4096
#define E_   1024
#define H_   16
#define HD_  64
#define BH_  32
#define M_   8192

// ==================== device scratch ====================
__device__ __align__(16) __half g_whi[4][E_ * E_];
__device__ __align__(16) __half g_wlo[4][E_ * E_];
__device__ __align__(16) __half g_xhi[M_ * E_];     // fp16(x)
__device__ __align__(16) __half g_ahi[M_ * E_];     // fp16(attn out)
__device__ __align__(16) __half g_qh[M_ * E_];      // fp16 q (pre-scaled by 0.125)
__device__ __align__(16) __half g_kh[M_ * E_];
__device__ __align__(16) __half g_vh[M_ * E_];
__device__ float g_attn[M_ * E_];
__device__ int   g_sidx[3][B_][N_];

// ==================== helpers ====================
__device__ __forceinline__ uint32_t smem_u32(const void* p) {
    uint32_t a;
    asm("{ .reg .u64 t; cvta.to.shared.u64 t, %1; cvt.u32.u64 %0, t; }" : "=r"(a) : "l"(p));
    return a;
}
__device__ __forceinline__ void cp16(uint32_t dst, const void* src) {
    asm volatile("cp.async.cg.shared.global [%0], [%1], 16;" :: "r"(dst), "l"(src));
}
#define CP_COMMIT() asm volatile("cp.async.commit_group;" ::: "memory")
#define CP_WAIT(n)  asm volatile("cp.async.wait_group %0;" :: "n"(n) : "memory")

__device__ __forceinline__ void mma16816(float* c, const uint32_t* a, uint32_t b0, uint32_t b1) {
    asm volatile(
        "mma.sync.aligned.m16n8k16.row.col.f32.f16.f16.f32 "
        "{%0,%1,%2,%3}, {%4,%5,%6,%7}, {%8,%9}, {%0,%1,%2,%3};"
        : "+f"(c[0]), "+f"(c[1]), "+f"(c[2]), "+f"(c[3])
        : "r"(a[0]), "r"(a[1]), "r"(a[2]), "r"(a[3]), "r"(b0), "r"(b1));
}
__device__ __forceinline__ void ldsm4(uint32_t addr, uint32_t* r) {
    asm volatile("ldmatrix.sync.aligned.m8n8.x4.shared.b16 {%0,%1,%2,%3}, [%4];"
                 : "=r"(r[0]), "=r"(r[1]), "=r"(r[2]), "=r"(r[3]) : "r"(addr));
}
__device__ __forceinline__ void ldsm4t(uint32_t addr, uint32_t* r) {
    asm volatile("ldmatrix.sync.aligned.m8n8.x4.trans.shared.b16 {%0,%1,%2,%3}, [%4];"
                 : "=r"(r[0]), "=r"(r[1]), "=r"(r[2]), "=r"(r[3]) : "r"(addr));
}
__device__ __forceinline__ uint32_t packh2(float a, float b) {
    __half2 h = __floats2half2_rn(a, b);
    return *(uint32_t*)&h;
}

// ==================== LoRA fold + fp16 hi/lo split (weights) ====================
__global__ void weff_kernel(const float* __restrict__ W, const float* __restrict__ A,
                            const float* __restrict__ Bm, int which) {
    int idx = blockIdx.x * 256 + threadIdx.x;
    int e = idx >> 10, k = idx & 1023;
    float acc = W[idx];
#pragma unroll
    for (int r = 0; r < 8; r++)
        acc = fmaf(2.0f * Bm[e * 8 + r], A[r * 1024 + k], acc);
    __half hi = __float2half_rn(acc);
    __half lo = __float2half_rn(acc - __half2float(hi));
    g_whi[which][idx] = hi;
    g_wlo[which][idx] = lo;
}

// ==================== fp32 -> fp16 conversion (x or attn) ====================
__global__ void cvt_kernel(const float* __restrict__ xsrc, int sel) {
    const float* src = sel ? g_attn : xsrc;
    __half* hi = sel ? g_ahi : g_xhi;
    int i = blockIdx.x * 256 + threadIdx.x;
    float4 v = ((const float4*)src)[i];
    __half2* hp = (__half2*)hi + 2 * i;
    hp[0] = __floats2half2_rn(v.x, v.y);
    hp[1] = __floats2half2_rn(v.z, v.w);
}

// ==================== stable argsort (bitonic on (bucket<<12)|pos) ====================
__global__ void sort_kernel(const int* __restrict__ wb0, const int* __restrict__ wb1,
                            const int* __restrict__ wb2) {
    int batch = blockIdx.x, level = blockIdx.y;
    const int* wb = (level == 0) ? wb0 : (level == 1) ? wb1 : wb2;
    __shared__ unsigned key[N_];
    int tid = threadIdx.x;
    for (int i = tid; i < N_; i += 1024)
        key[i] = ((unsigned)wb[batch * N_ + i] << 12) | (unsigned)i;
    __syncthreads();
    for (int k = 2; k <= N_; k <<= 1) {
        for (int j = k >> 1; j > 0; j >>= 1) {
            for (int t = tid; t < N_; t += 1024) {
                int ixj = t ^ j;
                if (ixj > t) {
                    unsigned a = key[t], b = key[ixj];
                    bool up = ((t & k) == 0);
                    if ((a > b) == up) { key[t] = b; key[ixj] = a; }
                }
            }
            __syncthreads();
        }
    }
    for (int i = tid; i < N_; i += 1024)
        g_sidx[level][batch][i] = (int)(key[i] & 0xFFFu);
}

// ==================== HMMA fp16 2-product GEMM ====================
static constexpr int TILEB = 128 * 128;
static constexpr int BUFB  = 3 * TILEB;
static constexpr int GEMM_SMEM = 2 * BUFB;              // 96KB

__global__ __launch_bounds__(512, 1) void gemm_tc(int qkv_mode,
                                                  const float* __restrict__ bias0,
                                                  const float* __restrict__ bias1,
                                                  const float* __restrict__ bias2,
                                                  float* __restrict__ out_ext) {
    extern __shared__ __align__(16) char dsm[];
    int z = blockIdx.z;
    const __half *Ah, *Bh, *Bl;
    const float* bias;
    if (qkv_mode) {
        Ah = g_xhi; Bh = g_whi[z]; Bl = g_wlo[z];
        bias = (z == 0) ? bias0 : (z == 1) ? bias1 : bias2;
    } else {
        Ah = g_ahi; Bh = g_whi[3]; Bl = g_wlo[3];
        bias = bias0;
    }

    int tid = threadIdx.x;
    int wid = tid >> 5, lane = tid & 31;
    int g = lane >> 2, t = lane & 3;
    int wm = wid >> 2, wn = wid & 3;
    int m0 = blockIdx.x * 128, n0 = blockIdx.y * 128;

    uint32_t sbase = smem_u32(dsm);
    const __half* srcs[3] = {
        Ah + (size_t)m0 * E_, Bh + (size_t)n0 * E_, Bl + (size_t)n0 * E_ };

    int lc = tid & 7, r6 = (tid >> 3) & 63;
    uint32_t cbyte = (uint32_t)(lc * 16);
    auto load_chunk = [&](int b, int kc) {
#pragma unroll
        for (int tgt = 0; tgt < 3; tgt++) {
            uint32_t tb = sbase + b * BUFB + tgt * TILEB;
            const __half* s = srcs[tgt] + kc * 64 + lc * 8;
#pragma unroll
            for (int p = 0; p < 2; p++) {
                int row = p * 64 + r6;
                cp16(tb + row * 128 + (cbyte ^ ((uint32_t)(row & 7) << 4)),
                     s + (size_t)row * E_);
            }
        }
        CP_COMMIT();
    };

    int lane7 = lane & 7, st = lane >> 3;
    int arow = wm * 32 + (st & 1) * 8 + lane7;
    uint32_t acolst = (uint32_t)((st >> 1) * 16);
    int brow = wn * 32 + (st >> 1) * 8 + lane7;
    uint32_t bcolst = (uint32_t)((st & 1) * 16);

    float acc[2][4][4];
#pragma unroll
    for (int i = 0; i < 2; i++)
#pragma unroll
        for (int j = 0; j < 4; j++)
#pragma unroll
            for (int q = 0; q < 4; q++) acc[i][j][q] = 0.f;

    load_chunk(0, 0);

    for (int kc = 0; kc < 16; kc++) {
        int b = kc & 1;
        if (kc + 1 < 16) { load_chunk(b ^ 1, kc + 1); CP_WAIT(1); }
        else             { CP_WAIT(0); }
        __syncthreads();

        uint32_t tA  = sbase + b * BUFB;
        uint32_t tB  = tA + TILEB;
        uint32_t tBl = tA + 2 * TILEB;

#pragma unroll
        for (int ks = 0; ks < 4; ks++) {
            uint32_t ko2 = (uint32_t)(ks * 32);
            uint32_t ah[2][4], bh[2][4], bl[2][4];
#pragma unroll
            for (int mi = 0; mi < 2; mi++) {
                int row = arow + mi * 16;
                uint32_t off = (uint32_t)(row * 128) + ((ko2 + acolst) ^ ((uint32_t)(row & 7) << 4));
                ldsm4(tA + off, ah[mi]);
            }
#pragma unroll
            for (int nb = 0; nb < 2; nb++) {
                int row = brow + nb * 16;
                uint32_t off = (uint32_t)(row * 128) + ((ko2 + bcolst) ^ ((uint32_t)(row & 7) << 4));
                ldsm4(tB + off, bh[nb]);
                ldsm4(tBl + off, bl[nb]);
            }
#pragma unroll
            for (int mi = 0; mi < 2; mi++)
#pragma unroll
                for (int ni = 0; ni < 4; ni++) {
                    int nb = ni >> 1, hf = (ni & 1) * 2;
                    mma16816(acc[mi][ni], ah[mi], bh[nb][hf], bh[nb][hf + 1]);
                    mma16816(acc[mi][ni], ah[mi], bl[nb][hf], bl[nb][hf + 1]);
                }
        }
        __syncthreads();
    }

    // epilogue
    if (qkv_mode) {
        __half* outh = (z == 0) ? g_qh : (z == 1) ? g_kh : g_vh;
        float scl = (z == 0) ? 0.125f : 1.0f;      // fold 1/sqrt(64) into q
#pragma unroll
        for (int mi = 0; mi < 2; mi++) {
            int r0 = m0 + wm * 32 + mi * 16 + g;
#pragma unroll
            for (int ni = 0; ni < 4; ni++) {
                int col = n0 + wn * 32 + ni * 8 + 2 * t;
                float bx = bias[col], by = bias[col + 1];
                *(__half2*)(outh + (size_t)r0 * E_ + col) =
                    __floats2half2_rn((acc[mi][ni][0] + bx) * scl, (acc[mi][ni][1] + by) * scl);
                *(__half2*)(outh + (size_t)(r0 + 8) * E_ + col) =
                    __floats2half2_rn((acc[mi][ni][2] + bx) * scl, (acc[mi][ni][3] + by) * scl);
            }
        }
    } else {
        float* out = out_ext;
#pragma unroll
        for (int mi = 0; mi < 2; mi++) {
            int r0 = m0 + wm * 32 + mi * 16 + g;
#pragma unroll
            for (int ni = 0; ni < 4; ni++) {
                int col = n0 + wn * 32 + ni * 8 + 2 * t;
                float bx = bias[col], by = bias[col + 1];
                float2 v0 = { acc[mi][ni][0] + bx, acc[mi][ni][1] + by };
                float2 v1 = { acc[mi][ni][2] + bx, acc[mi][ni][3] + by };
                *(float2*)(out + (size_t)r0 * E_ + col) = v0;
                *(float2*)(out + (size_t)(r0 + 8) * E_ + col) = v1;
            }
        }
    }
}

// ==================== flash-style MMA attention ====================
// 128 threads / 4 warps; 64-query tile per block; key tiles of 64 via smem.
// Warp w owns query rows [w*16, w*16+16). S = Q@K^T (mma), online softmax,
// O += P@V (mma, ldmatrix.trans on V). q pre-scaled by 1/8.
template <int LEVEL, bool FIRST>
__global__ __launch_bounds__(128) void attn_mma() {
    constexpr int C = (LEVEL == 0) ? 256 : (LEVEL == 1) ? 64 : 16;
    __shared__ __align__(16) __half sQ[64 * 64];
    __shared__ __align__(16) __half sK[64 * 64];
    __shared__ __align__(16) __half sV[64 * 64];

    int bh = blockIdx.x;
    int batch = bh >> 4, h = bh & 15;
    int qt = blockIdx.y;
    const int* sidx = &g_sidx[LEVEL][batch][0];
    int tid = threadIdx.x, wid = tid >> 5, lane = tid & 31;
    int g = lane >> 2, t = lane & 3;

    // block key window
    int klo, khi;
    if (LEVEL == 2) {
        int c0 = qt * 4;
        klo = (c0 == 0) ? 0 : 16 * (c0 - 1);
        khi = 16 * (c0 + 4);
    } else {
        int cg = (LEVEL == 0) ? (qt >> 2) : qt;
        klo = (cg == 0) ? 0 : (cg - 1) * C;
        khi = (cg + 1) * C;
    }
    int ntiles = (khi - klo + 63) >> 6;

    // warp window (level 2: each warp = one 16-query chunk)
    int wlo = klo, whi = khi;
    if (LEVEL == 2) {
        int cg = qt * 4 + wid;
        wlo = (cg == 0) ? 0 : 16 * cg - 16;
        whi = 16 * cg + 16;
    }

    // fill mapping: 16B chunk + base row
    int fc = tid & 7, fr = tid >> 3;
    uint32_t fcb = (uint32_t)(fc * 16);
    size_t hbase = (size_t)(batch * N_) * E_ + h * HD_;

    // load Q tile
#pragma unroll
    for (int p = 0; p < 4; p++) {
        int row = p * 16 + fr;
        int tok = sidx[qt * 64 + row];
        const uint4* src = (const uint4*)(g_qh + hbase + (size_t)tok * E_) + fc;
        uint32_t off = (uint32_t)(row * 128) + (fcb ^ ((uint32_t)(row & 7) << 4));
        *(uint4*)((char*)sQ + off) = *src;
    }
    __syncthreads();

    // Q fragments (kept in regs for whole kernel)
    int lane7 = lane & 7, st = lane >> 3;
    uint32_t aq[4][4];
    {
        int arow = wid * 16 + (st & 1) * 8 + lane7;
        uint32_t acol = (uint32_t)((st >> 1) * 16);
        uint32_t sq = smem_u32(sQ);
#pragma unroll
        for (int kk = 0; kk < 4; kk++) {
            uint32_t off = (uint32_t)(arow * 128) + ((acol + kk * 32) ^ ((uint32_t)(arow & 7) << 4));
            ldsm4(sq + off, aq[kk]);
        }
    }

    float o[8][4];
#pragma unroll
    for (int i = 0; i < 8; i++)
#pragma unroll
        for (int j = 0; j < 4; j++) o[i][j] = 0.f;
    float m0 = -1e30f, m1 = -1e30f, l0 = 0.f, l1 = 0.f;

    uint32_t sk = smem_u32(sK), sv = smem_u32(sV);
    int kbrow = (st >> 1) * 8 + lane7;                 // K b-frag (non-trans, like gemm B)
    uint32_t kbcol = (uint32_t)((st & 1) * 16);
    int vrow = (st & 1) * 8 + lane7;                   // V b-frag (trans)
    uint32_t vcol = (uint32_t)((lane >> 4) * 16);

    for (int tile = 0; tile < ntiles; tile++) {
        // fill K,V tiles (gathered rows, coalesced 128B)
#pragma unroll
        for (int p = 0; p < 4; p++) {
            int row = p * 16 + fr;
            int keyp = klo + tile * 64 + row;
            int tok = sidx[min(keyp, N_ - 1)];
            const uint4* ks = (const uint4*)(g_kh + hbase + (size_t)tok * E_) + fc;
            const uint4* vs = (const uint4*)(g_vh + hbase + (size_t)tok * E_) + fc;
            uint32_t off = (uint32_t)(row * 128) + (fcb ^ ((uint32_t)(row & 7) << 4));
            *(uint4*)((char*)sK + off) = *ks;
            *(uint4*)((char*)sV + off) = *vs;
        }
        __syncthreads();

        bool active = true;
        if (LEVEL == 2) {
            int tlo = klo + tile * 64;
            active = (wlo < tlo + 64) && (whi > tlo);
        }
        if (active) {
            // S = Q @ K^T
            float c[8][4];
#pragma unroll
            for (int i = 0; i < 8; i++)
#pragma unroll
                for (int j = 0; j < 4; j++) c[i][j] = 0.f;
#pragma unroll
            for (int kk = 0; kk < 4; kk++) {
                uint32_t ko2 = (uint32_t)(kk * 32);
#pragma unroll
                for (int nt = 0; nt < 4; nt++) {
                    int row = nt * 16 + kbrow;
                    uint32_t off = (uint32_t)(row * 128) + ((ko2 + kbcol) ^ ((uint32_t)(row & 7) << 4));
                    uint32_t bf[4];
                    ldsm4(sk + off, bf);
                    mma16816(c[2 * nt],     aq[kk], bf[0], bf[1]);
                    mma16816(c[2 * nt + 1], aq[kk], bf[2], bf[3]);
                }
            }
            // mask (level 2 only: warp-uniform window, per-column)
            if (LEVEL == 2) {
#pragma unroll
                for (int nt = 0; nt < 8; nt++) {
                    int col0 = klo + tile * 64 + nt * 8 + 2 * t;
                    if (col0 < wlo || col0 >= whi)     { c[nt][0] = -1e30f; c[nt][2] = -1e30f; }
                    if (col0 + 1 < wlo || col0 + 1 >= whi) { c[nt][1] = -1e30f; c[nt][3] = -1e30f; }
                }
            }
            // online softmax
            float mx0 = -1e30f, mx1 = -1e30f;
#pragma unroll
            for (int nt = 0; nt < 8; nt++) {
                mx0 = fmaxf(mx0, fmaxf(c[nt][0], c[nt][1]));
                mx1 = fmaxf(mx1, fmaxf(c[nt][2], c[nt][3]));
            }
            mx0 = fmaxf(mx0, __shfl_xor_sync(0xFFFFFFFFu, mx0, 1));
            mx0 = fmaxf(mx0, __shfl_xor_sync(0xFFFFFFFFu, mx0, 2));
            mx1 = fmaxf(mx1, __shfl_xor_sync(0xFFFFFFFFu, mx1, 1));
            mx1 = fmaxf(mx1, __shfl_xor_sync(0xFFFFFFFFu, mx1, 2));
            float mn0 = fmaxf(m0, mx0), mn1 = fmaxf(m1, mx1);
            float cr0 = __expf(m0 - mn0), cr1 = __expf(m1 - mn1);
            m0 = mn0; m1 = mn1;
            l0 *= cr0; l1 *= cr1;
            uint32_t pA[8], pB[8];
#pragma unroll
            for (int nt = 0; nt < 8; nt++) {
                float e0 = __expf(c[nt][0] - m0), e1 = __expf(c[nt][1] - m0);
                float e2 = __expf(c[nt][2] - m1), e3 = __expf(c[nt][3] - m1);
                l0 += e0 + e1; l1 += e2 + e3;
                pA[nt] = packh2(e0, e1);
                pB[nt] = packh2(e2, e3);
            }
#pragma unroll
            for (int ht = 0; ht < 8; ht++) {
                o[ht][0] *= cr0; o[ht][1] *= cr0;
                o[ht][2] *= cr1; o[ht][3] *= cr1;
            }
            // O += P @ V
#pragma unroll
            for (int kj = 0; kj < 4; kj++) {
                uint32_t a[4] = { pA[2 * kj], pB[2 * kj], pA[2 * kj + 1], pB[2 * kj + 1] };
#pragma unroll
                for (int ht = 0; ht < 4; ht++) {
                    int row = kj * 16 + vrow;
                    uint32_t off = (uint32_t)(row * 128) +
                                   (((uint32_t)(ht * 32) + vcol) ^ ((uint32_t)(row & 7) << 4));
                    uint32_t b[4];
                    ldsm4t(sv + off, b);
                    mma16816(o[2 * ht],     a, b[0], b[1]);
                    mma16816(o[2 * ht + 1], a, b[2], b[3]);
                }
            }
        }
        __syncthreads();
    }

    // reduce l across quad, write output
    l0 += __shfl_xor_sync(0xFFFFFFFFu, l0, 1);
    l0 += __shfl_xor_sync(0xFFFFFFFFu, l0, 2);
    l1 += __shfl_xor_sync(0xFFFFFFFFu, l1, 1);
    l1 += __shfl_xor_sync(0xFFFFFFFFu, l1, 2);
    float inv0 = 1.f / (3.f * l0);
    float inv1 = 1.f / (3.f * l1);

    int pq0 = qt * 64 + wid * 16 + g;
    int tok0 = sidx[pq0];
    int tok1 = sidx[pq0 + 8];
    float* d0 = g_attn + (size_t)(batch * N_ + tok0) * E_ + h * HD_;
    float* d1 = g_attn + (size_t)(batch * N_ + tok1) * E_ + h * HD_;
#pragma unroll
    for (int nt = 0; nt < 8; nt++) {
        int col = nt * 8 + 2 * t;
        float2 v0 = { o[nt][0] * inv0, o[nt][1] * inv0 };
        float2 v1 = { o[nt][2] * inv1, o[nt][3] * inv1 };
        if (FIRST) {
            *(float2*)(d0 + col) = v0;
            *(float2*)(d1 + col) = v1;
        } else {
            float2 u0 = *(float2*)(d0 + col);
            float2 u1 = *(float2*)(d1 + col);
            u0.x += v0.x; u0.y += v0.y;
            u1.x += v1.x; u1.y += v1.y;
            *(float2*)(d0 + col) = u0;
            *(float2*)(d1 + col) = u1;
        }
    }
}

// ==================== launch ====================
extern "C" void kernel_launch(void* const* d_in, const int* in_sizes, int n_in,
                              void* d_out, int out_size) {
    (void)in_sizes; (void)n_in; (void)out_size;
    const float* x   = (const float*)d_in[0];
    const int*   wbc = (const int*)d_in[1];
    const int*   wbm = (const int*)d_in[2];
    const int*   wbf = (const int*)d_in[3];
    const float* Wp[4] = { (const float*)d_in[4],  (const float*)d_in[8],
                           (const float*)d_in[12], (const float*)d_in[16] };
    const float* bp[4] = { (const float*)d_in[5],  (const float*)d_in[9],
                           (const float*)d_in[13], (const float*)d_in[17] };
    const float* Ap[4] = { (const float*)d_in[6],  (const float*)d_in[10],
                           (const float*)d_in[14], (const float*)d_in[18] };
    const float* Lp[4] = { (const float*)d_in[7],  (const float*)d_in[11],
                           (const float*)d_in[15], (const float*)d_in[19] };
    float* out = (float*)d_out;

    cudaFuncSetAttribute(gemm_tc, cudaFuncAttributeMaxDynamicSharedMemorySize, GEMM_SMEM);

    // 1) fold LoRA + split weights to fp16 hi/lo
    for (int p = 0; p < 4; p++)
        weff_kernel<<<(E_ * E_) / 256, 256>>>(Wp[p], Ap[p], Lp[p], p);

    // 2) convert x to fp16
    cvt_kernel<<<(M_ * E_ / 4) / 256, 256>>>(x, 0);

    // 3) fused q,k,v projections -> fp16 (q pre-scaled by 1/8)
    gemm_tc<<<dim3(M_ / 128, E_ / 128, 3), 512, GEMM_SMEM>>>(1, bp[0], bp[1], bp[2], nullptr);

    // 4) stable argsort per (batch, level)
    sort_kernel<<<dim3(B_, 3), 1024>>>(wbc, wbm, wbf);

    // 5) three-level flash-MMA attention
    attn_mma<0, true ><<<dim3(BH_, N_ / 64), 128>>>();
    attn_mma<1, false><<<dim3(BH_, N_ / 64), 128>>>();
    attn_mma<2, false><<<dim3(BH_, N_ / 64), 128>>>();

    // 6) convert attention output to fp16
    cvt_kernel<<<(M_ * E_ / 4) / 256, 256>>>(nullptr, 1);

    // 7) output projection
    gemm_tc<<<dim3(M_ / 128, E_ / 128, 1), 512, GEMM_SMEM>>>(0, bp[3], nullptr, nullptr, out);
}

// round 8
// speedup vs baseline: 4.2632x; 1.0839x over previous
#include <cuda_runtime.h>
#include <cuda_fp16.h>
#include <math.h>
#include <stdint.h>

#define B_   2
#define N_   4096
#define E_   1024
#define H_   16
#define HD_  64
#define BH_  32
#define M_   8192
#define MSZ  (M_ * E_)

// ==================== device scratch ====================
__device__ __align__(16) __half g_whi[4][E_ * E_];
__device__ __align__(16) __half g_wlo[4][E_ * E_];
__device__ __align__(16) __half g_xhi[MSZ];       // fp16(x)
__device__ __align__(16) __half g_ahi[MSZ];       // fp16(attn out, summed)
__device__ __align__(16) __half g_qh[MSZ];        // fp16 q (pre-scaled by 0.125)
__device__ __align__(16) __half g_kh[MSZ];
__device__ __align__(16) __half g_vh[MSZ];
__device__ __align__(16) float g_attn3[3][MSZ];   // per-level attention outputs
__device__ int g_sidx[3][B_][N_];

// ==================== helpers ====================
__device__ __forceinline__ uint32_t smem_u32(const void* p) {
    uint32_t a;
    asm("{ .reg .u64 t; cvta.to.shared.u64 t, %1; cvt.u32.u64 %0, t; }" : "=r"(a) : "l"(p));
    return a;
}
__device__ __forceinline__ void cp16(uint32_t dst, const void* src) {
    asm volatile("cp.async.cg.shared.global [%0], [%1], 16;" :: "r"(dst), "l"(src));
}
#define CP_COMMIT() asm volatile("cp.async.commit_group;" ::: "memory")
#define CP_WAIT(n)  asm volatile("cp.async.wait_group %0;" :: "n"(n) : "memory")

__device__ __forceinline__ void mma16816(float* c, const uint32_t* a, uint32_t b0, uint32_t b1) {
    asm volatile(
        "mma.sync.aligned.m16n8k16.row.col.f32.f16.f16.f32 "
        "{%0,%1,%2,%3}, {%4,%5,%6,%7}, {%8,%9}, {%0,%1,%2,%3};"
        : "+f"(c[0]), "+f"(c[1]), "+f"(c[2]), "+f"(c[3])
        : "r"(a[0]), "r"(a[1]), "r"(a[2]), "r"(a[3]), "r"(b0), "r"(b1));
}
__device__ __forceinline__ void ldsm4(uint32_t addr, uint32_t* r) {
    asm volatile("ldmatrix.sync.aligned.m8n8.x4.shared.b16 {%0,%1,%2,%3}, [%4];"
                 : "=r"(r[0]), "=r"(r[1]), "=r"(r[2]), "=r"(r[3]) : "r"(addr));
}
__device__ __forceinline__ void ldsm4t(uint32_t addr, uint32_t* r) {
    asm volatile("ldmatrix.sync.aligned.m8n8.x4.trans.shared.b16 {%0,%1,%2,%3}, [%4];"
                 : "=r"(r[0]), "=r"(r[1]), "=r"(r[2]), "=r"(r[3]) : "r"(addr));
}
__device__ __forceinline__ uint32_t packh2(float a, float b) {
    __half2 h = __floats2half2_rn(a, b);
    return *(uint32_t*)&h;
}

// ==================== fused LoRA fold + fp16 hi/lo split (all 4 projections) ====================
__global__ void weff_kernel(const float* __restrict__ W0, const float* __restrict__ A0, const float* __restrict__ B0,
                            const float* __restrict__ W1, const float* __restrict__ A1, const float* __restrict__ B1,
                            const float* __restrict__ W2, const float* __restrict__ A2, const float* __restrict__ B2,
                            const float* __restrict__ W3, const float* __restrict__ A3, const float* __restrict__ B3) {
    int which = blockIdx.y;
    const float* W = (which == 0) ? W0 : (which == 1) ? W1 : (which == 2) ? W2 : W3;
    const float* A = (which == 0) ? A0 : (which == 1) ? A1 : (which == 2) ? A2 : A3;
    const float* Bm = (which == 0) ? B0 : (which == 1) ? B1 : (which == 2) ? B2 : B3;
    int idx = blockIdx.x * 256 + threadIdx.x;
    int e = idx >> 10, k = idx & 1023;
    float acc = W[idx];
#pragma unroll
    for (int r = 0; r < 8; r++)
        acc = fmaf(2.0f * Bm[e * 8 + r], A[r * 1024 + k], acc);
    __half hi = __float2half_rn(acc);
    __half lo = __float2half_rn(acc - __half2float(hi));
    g_whi[which][idx] = hi;
    g_wlo[which][idx] = lo;
}

// ==================== fp32 -> fp16 conversion (x) ====================
__global__ void cvt_kernel(const float* __restrict__ src) {
    int i = blockIdx.x * 256 + threadIdx.x;
    float4 v = ((const float4*)src)[i];
    __half2* hp = (__half2*)g_xhi + 2 * i;
    hp[0] = __floats2half2_rn(v.x, v.y);
    hp[1] = __floats2half2_rn(v.z, v.w);
}

// ==================== sum 3 attention levels -> fp16 ====================
__global__ void cvt_sum_kernel() {
    int i = blockIdx.x * 256 + threadIdx.x;
    float4 a = ((const float4*)g_attn3[0])[i];
    float4 b = ((const float4*)g_attn3[1])[i];
    float4 c = ((const float4*)g_attn3[2])[i];
    __half2* hp = (__half2*)g_ahi + 2 * i;
    hp[0] = __floats2half2_rn(a.x + b.x + c.x, a.y + b.y + c.y);
    hp[1] = __floats2half2_rn(a.z + b.z + c.z, a.w + b.w + c.w);
}

// ==================== stable argsort (bitonic on (bucket<<12)|pos) ====================
__global__ void sort_kernel(const int* __restrict__ wb0, const int* __restrict__ wb1,
                            const int* __restrict__ wb2) {
    int batch = blockIdx.x, level = blockIdx.y;
    const int* wb = (level == 0) ? wb0 : (level == 1) ? wb1 : wb2;
    __shared__ unsigned key[N_];
    int tid = threadIdx.x;
    for (int i = tid; i < N_; i += 1024)
        key[i] = ((unsigned)wb[batch * N_ + i] << 12) | (unsigned)i;
    __syncthreads();
    for (int k = 2; k <= N_; k <<= 1) {
        for (int j = k >> 1; j > 0; j >>= 1) {
            for (int t = tid; t < N_; t += 1024) {
                int ixj = t ^ j;
                if (ixj > t) {
                    unsigned a = key[t], b = key[ixj];
                    bool up = ((t & k) == 0);
                    if ((a > b) == up) { key[t] = b; key[ixj] = a; }
                }
            }
            __syncthreads();
        }
    }
    for (int i = tid; i < N_; i += 1024)
        g_sidx[level][batch][i] = (int)(key[i] & 0xFFFu);
}

// ==================== HMMA fp16 2-product GEMM (unchanged, proven) ====================
static constexpr int TILEB = 128 * 128;
static constexpr int BUFB  = 3 * TILEB;
static constexpr int GEMM_SMEM = 2 * BUFB;              // 96KB

__global__ __launch_bounds__(512, 1) void gemm_tc(int qkv_mode,
                                                  const float* __restrict__ bias0,
                                                  const float* __restrict__ bias1,
                                                  const float* __restrict__ bias2,
                                                  float* __restrict__ out_ext) {
    extern __shared__ __align__(16) char dsm[];
    int z = blockIdx.z;
    const __half *Ah, *Bh, *Bl;
    const float* bias;
    if (qkv_mode) {
        Ah = g_xhi; Bh = g_whi[z]; Bl = g_wlo[z];
        bias = (z == 0) ? bias0 : (z == 1) ? bias1 : bias2;
    } else {
        Ah = g_ahi; Bh = g_whi[3]; Bl = g_wlo[3];
        bias = bias0;
    }

    int tid = threadIdx.x;
    int wid = tid >> 5, lane = tid & 31;
    int g = lane >> 2, t = lane & 3;
    int wm = wid >> 2, wn = wid & 3;
    int m0 = blockIdx.x * 128, n0 = blockIdx.y * 128;

    uint32_t sbase = smem_u32(dsm);
    const __half* srcs[3] = {
        Ah + (size_t)m0 * E_, Bh + (size_t)n0 * E_, Bl + (size_t)n0 * E_ };

    int lc = tid & 7, r6 = (tid >> 3) & 63;
    uint32_t cbyte = (uint32_t)(lc * 16);
    auto load_chunk = [&](int b, int kc) {
#pragma unroll
        for (int tgt = 0; tgt < 3; tgt++) {
            uint32_t tb = sbase + b * BUFB + tgt * TILEB;
            const __half* s = srcs[tgt] + kc * 64 + lc * 8;
#pragma unroll
            for (int p = 0; p < 2; p++) {
                int row = p * 64 + r6;
                cp16(tb + row * 128 + (cbyte ^ ((uint32_t)(row & 7) << 4)),
                     s + (size_t)row * E_);
            }
        }
        CP_COMMIT();
    };

    int lane7 = lane & 7, st = lane >> 3;
    int arow = wm * 32 + (st & 1) * 8 + lane7;
    uint32_t acolst = (uint32_t)((st >> 1) * 16);
    int brow = wn * 32 + (st >> 1) * 8 + lane7;
    uint32_t bcolst = (uint32_t)((st & 1) * 16);

    float acc[2][4][4];
#pragma unroll
    for (int i = 0; i < 2; i++)
#pragma unroll
        for (int j = 0; j < 4; j++)
#pragma unroll
            for (int q = 0; q < 4; q++) acc[i][j][q] = 0.f;

    load_chunk(0, 0);

    for (int kc = 0; kc < 16; kc++) {
        int b = kc & 1;
        if (kc + 1 < 16) { load_chunk(b ^ 1, kc + 1); CP_WAIT(1); }
        else             { CP_WAIT(0); }
        __syncthreads();

        uint32_t tA  = sbase + b * BUFB;
        uint32_t tB  = tA + TILEB;
        uint32_t tBl = tA + 2 * TILEB;

#pragma unroll
        for (int ks = 0; ks < 4; ks++) {
            uint32_t ko2 = (uint32_t)(ks * 32);
            uint32_t ah[2][4], bh[2][4], bl[2][4];
#pragma unroll
            for (int mi = 0; mi < 2; mi++) {
                int row = arow + mi * 16;
                uint32_t off = (uint32_t)(row * 128) + ((ko2 + acolst) ^ ((uint32_t)(row & 7) << 4));
                ldsm4(tA + off, ah[mi]);
            }
#pragma unroll
            for (int nb = 0; nb < 2; nb++) {
                int row = brow + nb * 16;
                uint32_t off = (uint32_t)(row * 128) + ((ko2 + bcolst) ^ ((uint32_t)(row & 7) << 4));
                ldsm4(tB + off, bh[nb]);
                ldsm4(tBl + off, bl[nb]);
            }
#pragma unroll
            for (int mi = 0; mi < 2; mi++)
#pragma unroll
                for (int ni = 0; ni < 4; ni++) {
                    int nb = ni >> 1, hf = (ni & 1) * 2;
                    mma16816(acc[mi][ni], ah[mi], bh[nb][hf], bh[nb][hf + 1]);
                    mma16816(acc[mi][ni], ah[mi], bl[nb][hf], bl[nb][hf + 1]);
                }
        }
        __syncthreads();
    }

    if (qkv_mode) {
        __half* outh = (z == 0) ? g_qh : (z == 1) ? g_kh : g_vh;
        float scl = (z == 0) ? 0.125f : 1.0f;
#pragma unroll
        for (int mi = 0; mi < 2; mi++) {
            int r0 = m0 + wm * 32 + mi * 16 + g;
#pragma unroll
            for (int ni = 0; ni < 4; ni++) {
                int col = n0 + wn * 32 + ni * 8 + 2 * t;
                float bx = bias[col], by = bias[col + 1];
                *(__half2*)(outh + (size_t)r0 * E_ + col) =
                    __floats2half2_rn((acc[mi][ni][0] + bx) * scl, (acc[mi][ni][1] + by) * scl);
                *(__half2*)(outh + (size_t)(r0 + 8) * E_ + col) =
                    __floats2half2_rn((acc[mi][ni][2] + bx) * scl, (acc[mi][ni][3] + by) * scl);
            }
        }
    } else {
        float* out = out_ext;
#pragma unroll
        for (int mi = 0; mi < 2; mi++) {
            int r0 = m0 + wm * 32 + mi * 16 + g;
#pragma unroll
            for (int ni = 0; ni < 4; ni++) {
                int col = n0 + wn * 32 + ni * 8 + 2 * t;
                float bx = bias[col], by = bias[col + 1];
                float2 v0 = { acc[mi][ni][0] + bx, acc[mi][ni][1] + by };
                float2 v1 = { acc[mi][ni][2] + bx, acc[mi][ni][3] + by };
                *(float2*)(out + (size_t)r0 * E_ + col) = v0;
                *(float2*)(out + (size_t)(r0 + 8) * E_ + col) = v1;
            }
        }
    }
}

// ==================== fused flash-MMA attention (all 3 levels, cp.async pipelined) ====================
// grid (BH, 64, 3); 128 threads / 4 warps; 64-query tile; 64-key tiles double-buffered.
__global__ __launch_bounds__(128) void attn_mma() {
    __shared__ __align__(16) __half sQ[64 * 64];
    __shared__ __align__(16) __half sK[2][64 * 64];
    __shared__ __align__(16) __half sV[2][64 * 64];

    int bh = blockIdx.x;
    int batch = bh >> 4, h = bh & 15;
    int qt = blockIdx.y;
    int level = blockIdx.z;
    const int* sidx = &g_sidx[level][batch][0];
    int tid = threadIdx.x, wid = tid >> 5, lane = tid & 31;
    int g = lane >> 2, t = lane & 3;

    // key windows
    int klo, khi, wlo, whi;
    if (level == 2) {
        int c0 = qt * 4;
        klo = c0 ? 16 * (c0 - 1) : 0;
        khi = 16 * (c0 + 4);
        int cg = c0 + wid;
        wlo = cg ? 16 * cg - 16 : 0;
        whi = 16 * cg + 16;
    } else {
        int C = level ? 64 : 256;
        int cg = level ? qt : (qt >> 2);
        klo = cg ? (cg - 1) * C : 0;
        khi = (cg + 1) * C;
        wlo = klo; whi = khi;
    }
    int ntiles = (khi - klo + 63) >> 6;

    int fc = tid & 7, fr = tid >> 3;
    uint32_t fcb = (uint32_t)(fc * 16);
    size_t hbase = (size_t)(batch * N_) * E_ + h * HD_;
    uint32_t sq = smem_u32(sQ);
    uint32_t skb[2] = { smem_u32(sK[0]), smem_u32(sK[1]) };
    uint32_t svb[2] = { smem_u32(sV[0]), smem_u32(sV[1]) };

    auto load_kv = [&](int buf, int tile) {
#pragma unroll
        for (int p = 0; p < 4; p++) {
            int row = p * 16 + fr;
            int tok = sidx[klo + tile * 64 + row];
            uint32_t off = (uint32_t)(row * 128) + (fcb ^ ((uint32_t)(row & 7) << 4));
            cp16(skb[buf] + off, (const uint4*)(g_kh + hbase + (size_t)tok * E_) + fc);
            cp16(svb[buf] + off, (const uint4*)(g_vh + hbase + (size_t)tok * E_) + fc);
        }
        CP_COMMIT();
    };

    // prefetch Q + KV tile 0 (one group)
#pragma unroll
    for (int p = 0; p < 4; p++) {
        int row = p * 16 + fr;
        int tok = sidx[qt * 64 + row];
        uint32_t off = (uint32_t)(row * 128) + (fcb ^ ((uint32_t)(row & 7) << 4));
        cp16(sq + off, (const uint4*)(g_qh + hbase + (size_t)tok * E_) + fc);
    }
    load_kv(0, 0);

    int lane7 = lane & 7, st = lane >> 3;
    int kbrow = (st >> 1) * 8 + lane7;
    uint32_t kbcol = (uint32_t)((st & 1) * 16);
    int vrow = (st & 1) * 8 + lane7;
    uint32_t vcol = (uint32_t)((lane >> 4) * 16);

    uint32_t aq[4][4];
    float o[8][4];
#pragma unroll
    for (int i = 0; i < 8; i++)
#pragma unroll
        for (int j = 0; j < 4; j++) o[i][j] = 0.f;
    float m0 = -1e30f, m1 = -1e30f, l0 = 0.f, l1 = 0.f;

    for (int tile = 0; tile < ntiles; tile++) {
        int buf = tile & 1;
        CP_WAIT(0);
        __syncthreads();
        if (tile == 0) {
            int arow = wid * 16 + (st & 1) * 8 + lane7;
            uint32_t acol = (uint32_t)((st >> 1) * 16);
#pragma unroll
            for (int kk = 0; kk < 4; kk++) {
                uint32_t off = (uint32_t)(arow * 128) + ((acol + kk * 32) ^ ((uint32_t)(arow & 7) << 4));
                ldsm4(sq + off, aq[kk]);
            }
        }
        if (tile + 1 < ntiles) load_kv(buf ^ 1, tile + 1);

        bool active = true;
        if (level == 2) {
            int tlo = klo + tile * 64;
            active = (wlo < tlo + 64) && (whi > tlo);
        }
        if (active) {
            uint32_t sk = skb[buf], sv = svb[buf];
            float c[8][4];
#pragma unroll
            for (int i = 0; i < 8; i++)
#pragma unroll
                for (int j = 0; j < 4; j++) c[i][j] = 0.f;
#pragma unroll
            for (int kk = 0; kk < 4; kk++) {
                uint32_t ko2 = (uint32_t)(kk * 32);
#pragma unroll
                for (int nt = 0; nt < 4; nt++) {
                    int row = nt * 16 + kbrow;
                    uint32_t off = (uint32_t)(row * 128) + ((ko2 + kbcol) ^ ((uint32_t)(row & 7) << 4));
                    uint32_t bf[4];
                    ldsm4(sk + off, bf);
                    mma16816(c[2 * nt],     aq[kk], bf[0], bf[1]);
                    mma16816(c[2 * nt + 1], aq[kk], bf[2], bf[3]);
                }
            }
            if (level == 2) {
#pragma unroll
                for (int nt = 0; nt < 8; nt++) {
                    int col0 = klo + tile * 64 + nt * 8 + 2 * t;
                    if (col0 < wlo || col0 >= whi)         { c[nt][0] = -1e30f; c[nt][2] = -1e30f; }
                    if (col0 + 1 < wlo || col0 + 1 >= whi) { c[nt][1] = -1e30f; c[nt][3] = -1e30f; }
                }
            }
            float mx0 = -1e30f, mx1 = -1e30f;
#pragma unroll
            for (int nt = 0; nt < 8; nt++) {
                mx0 = fmaxf(mx0, fmaxf(c[nt][0], c[nt][1]));
                mx1 = fmaxf(mx1, fmaxf(c[nt][2], c[nt][3]));
            }
            mx0 = fmaxf(mx0, __shfl_xor_sync(0xFFFFFFFFu, mx0, 1));
            mx0 = fmaxf(mx0, __shfl_xor_sync(0xFFFFFFFFu, mx0, 2));
            mx1 = fmaxf(mx1, __shfl_xor_sync(0xFFFFFFFFu, mx1, 1));
            mx1 = fmaxf(mx1, __shfl_xor_sync(0xFFFFFFFFu, mx1, 2));
            float mn0 = fmaxf(m0, mx0), mn1 = fmaxf(m1, mx1);
            float cr0 = __expf(m0 - mn0), cr1 = __expf(m1 - mn1);
            m0 = mn0; m1 = mn1;
            l0 *= cr0; l1 *= cr1;
            uint32_t pA[8], pB[8];
#pragma unroll
            for (int nt = 0; nt < 8; nt++) {
                float e0 = __expf(c[nt][0] - m0), e1 = __expf(c[nt][1] - m0);
                float e2 = __expf(c[nt][2] - m1), e3 = __expf(c[nt][3] - m1);
                l0 += e0 + e1; l1 += e2 + e3;
                pA[nt] = packh2(e0, e1);
                pB[nt] = packh2(e2, e3);
            }
#pragma unroll
            for (int ht = 0; ht < 8; ht++) {
                o[ht][0] *= cr0; o[ht][1] *= cr0;
                o[ht][2] *= cr1; o[ht][3] *= cr1;
            }
#pragma unroll
            for (int kj = 0; kj < 4; kj++) {
                uint32_t a[4] = { pA[2 * kj], pB[2 * kj], pA[2 * kj + 1], pB[2 * kj + 1] };
#pragma unroll
                for (int ht = 0; ht < 4; ht++) {
                    int row = kj * 16 + vrow;
                    uint32_t off = (uint32_t)(row * 128) +
                                   (((uint32_t)(ht * 32) + vcol) ^ ((uint32_t)(row & 7) << 4));
                    uint32_t b[4];
                    ldsm4t(sv + off, b);
                    mma16816(o[2 * ht],     a, b[0], b[1]);
                    mma16816(o[2 * ht + 1], a, b[2], b[3]);
                }
            }
        }
        __syncthreads();
    }

    l0 += __shfl_xor_sync(0xFFFFFFFFu, l0, 1);
    l0 += __shfl_xor_sync(0xFFFFFFFFu, l0, 2);
    l1 += __shfl_xor_sync(0xFFFFFFFFu, l1, 1);
    l1 += __shfl_xor_sync(0xFFFFFFFFu, l1, 2);
    float inv0 = 1.f / (3.f * l0);
    float inv1 = 1.f / (3.f * l1);

    int pq0 = qt * 64 + wid * 16 + g;
    int tok0 = sidx[pq0];
    int tok1 = sidx[pq0 + 8];
    float* base = g_attn3[level];
    float* d0 = base + (size_t)(batch * N_ + tok0) * E_ + h * HD_;
    float* d1 = base + (size_t)(batch * N_ + tok1) * E_ + h * HD_;
#pragma unroll
    for (int nt = 0; nt < 8; nt++) {
        int col = nt * 8 + 2 * t;
        float2 v0 = { o[nt][0] * inv0, o[nt][1] * inv0 };
        float2 v1 = { o[nt][2] * inv1, o[nt][3] * inv1 };
        *(float2*)(d0 + col) = v0;
        *(float2*)(d1 + col) = v1;
    }
}

// ==================== launch ====================
extern "C" void kernel_launch(void* const* d_in, const int* in_sizes, int n_in,
                              void* d_out, int out_size) {
    (void)in_sizes; (void)n_in; (void)out_size;
    const float* x   = (const float*)d_in[0];
    const int*   wbc = (const int*)d_in[1];
    const int*   wbm = (const int*)d_in[2];
    const int*   wbf = (const int*)d_in[3];
    const float* Wp[4] = { (const float*)d_in[4],  (const float*)d_in[8],
                           (const float*)d_in[12], (const float*)d_in[16] };
    const float* bp[4] = { (const float*)d_in[5],  (const float*)d_in[9],
                           (const float*)d_in[13], (const float*)d_in[17] };
    const float* Ap[4] = { (const float*)d_in[6],  (const float*)d_in[10],
                           (const float*)d_in[14], (const float*)d_in[18] };
    const float* Lp[4] = { (const float*)d_in[7],  (const float*)d_in[11],
                           (const float*)d_in[15], (const float*)d_in[19] };
    float* out = (float*)d_out;

    cudaFuncSetAttribute(gemm_tc, cudaFuncAttributeMaxDynamicSharedMemorySize, GEMM_SMEM);

    // 1) fused LoRA fold + fp16 hi/lo split (all 4 projections)
    weff_kernel<<<dim3((E_ * E_) / 256, 4), 256>>>(
        Wp[0], Ap[0], Lp[0], Wp[1], Ap[1], Lp[1],
        Wp[2], Ap[2], Lp[2], Wp[3], Ap[3], Lp[3]);

    // 2) convert x to fp16
    cvt_kernel<<<(MSZ / 4) / 256, 256>>>(x);

    // 3) fused q,k,v projections -> fp16 (q pre-scaled by 1/8)
    gemm_tc<<<dim3(M_ / 128, E_ / 128, 3), 512, GEMM_SMEM>>>(1, bp[0], bp[1], bp[2], nullptr);

    // 4) stable argsort per (batch, level)
    sort_kernel<<<dim3(B_, 3), 1024>>>(wbc, wbm, wbf);

    // 5) fused three-level flash-MMA attention (per-level output buffers)
    attn_mma<<<dim3(BH_, N_ / 64, 3), 128>>>();

    // 6) sum levels + convert to fp16
    cvt_sum_kernel<<<(MSZ / 4) / 256, 256>>>();

    // 7) output projection
    gemm_tc<<<dim3(M_ / 128, E_ / 128, 1), 512, GEMM_SMEM>>>(0, bp[3], nullptr, nullptr, out);
}

// round 9
// speedup vs baseline: 4.4173x; 1.0362x over previous
#include <cuda_runtime.h>
#include <cuda_fp16.h>
#include <math.h>
#include <stdint.h>

#define B_   2
#define N_   4096
#define E_   1024
#define H_   16
#define HD_  64
#define BH_  32
#define M_   8192
#define MSZ  (M_ * E_)

// ==================== device scratch ====================
__device__ __align__(16) __half g_whi[4][E_ * E_];
__device__ __align__(16) __half g_wlo[4][E_ * E_];
__device__ __align__(16) __half g_xhi[MSZ];       // fp16(x)
__device__ __align__(16) __half g_ahi[MSZ];       // fp16(attn out, summed)
__device__ __align__(16) __half g_qh[MSZ];        // fp16 q (pre-scaled by 0.125)
__device__ __align__(16) __half g_kh[MSZ];
__device__ __align__(16) __half g_vh[MSZ];
__device__ __align__(16) float g_attn3[3][MSZ];   // per-level attention outputs
__device__ int g_sidx[3][B_][N_];

// ==================== helpers ====================
__device__ __forceinline__ uint32_t smem_u32(const void* p) {
    uint32_t a;
    asm("{ .reg .u64 t; cvta.to.shared.u64 t, %1; cvt.u32.u64 %0, t; }" : "=r"(a) : "l"(p));
    return a;
}
__device__ __forceinline__ void cp16(uint32_t dst, const void* src) {
    asm volatile("cp.async.cg.shared.global [%0], [%1], 16;" :: "r"(dst), "l"(src));
}
#define CP_COMMIT() asm volatile("cp.async.commit_group;" ::: "memory")
#define CP_WAIT(n)  asm volatile("cp.async.wait_group %0;" :: "n"(n) : "memory")

__device__ __forceinline__ void mma16816(float* c, const uint32_t* a, uint32_t b0, uint32_t b1) {
    asm volatile(
        "mma.sync.aligned.m16n8k16.row.col.f32.f16.f16.f32 "
        "{%0,%1,%2,%3}, {%4,%5,%6,%7}, {%8,%9}, {%0,%1,%2,%3};"
        : "+f"(c[0]), "+f"(c[1]), "+f"(c[2]), "+f"(c[3])
        : "r"(a[0]), "r"(a[1]), "r"(a[2]), "r"(a[3]), "r"(b0), "r"(b1));
}
__device__ __forceinline__ void ldsm4(uint32_t addr, uint32_t* r) {
    asm volatile("ldmatrix.sync.aligned.m8n8.x4.shared.b16 {%0,%1,%2,%3}, [%4];"
                 : "=r"(r[0]), "=r"(r[1]), "=r"(r[2]), "=r"(r[3]) : "r"(addr));
}
__device__ __forceinline__ void ldsm4t(uint32_t addr, uint32_t* r) {
    asm volatile("ldmatrix.sync.aligned.m8n8.x4.trans.shared.b16 {%0,%1,%2,%3}, [%4];"
                 : "=r"(r[0]), "=r"(r[1]), "=r"(r[2]), "=r"(r[3]) : "r"(addr));
}
__device__ __forceinline__ uint32_t packh2(float a, float b) {
    __half2 h = __floats2half2_rn(a, b);
    return *(uint32_t*)&h;
}

// ==================== fused prep: LoRA fold (y<4) + x->fp16 (y>=4) ====================
__global__ void prep_kernel(const float* __restrict__ W0, const float* __restrict__ A0, const float* __restrict__ B0,
                            const float* __restrict__ W1, const float* __restrict__ A1, const float* __restrict__ B1,
                            const float* __restrict__ W2, const float* __restrict__ A2, const float* __restrict__ B2,
                            const float* __restrict__ W3, const float* __restrict__ A3, const float* __restrict__ B3,
                            const float* __restrict__ x) {
    int y = blockIdx.y;
    if (y < 4) {
        const float* W = (y == 0) ? W0 : (y == 1) ? W1 : (y == 2) ? W2 : W3;
        const float* A = (y == 0) ? A0 : (y == 1) ? A1 : (y == 2) ? A2 : A3;
        const float* Bm = (y == 0) ? B0 : (y == 1) ? B1 : (y == 2) ? B2 : B3;
        int idx = blockIdx.x * 256 + threadIdx.x;
        int e = idx >> 10, k = idx & 1023;
        float acc = W[idx];
#pragma unroll
        for (int r = 0; r < 8; r++)
            acc = fmaf(2.0f * Bm[e * 8 + r], A[r * 1024 + k], acc);
        __half hi = __float2half_rn(acc);
        __half lo = __float2half_rn(acc - __half2float(hi));
        g_whi[y][idx] = hi;
        g_wlo[y][idx] = lo;
    } else {
        int i = (blockIdx.x + (y - 4) * 4096) * 256 + threadIdx.x;  // 0 .. MSZ/4
        float4 v = ((const float4*)x)[i];
        __half2* hp = (__half2*)g_xhi + 2 * i;
        hp[0] = __floats2half2_rn(v.x, v.y);
        hp[1] = __floats2half2_rn(v.z, v.w);
    }
}

// ==================== sum 3 attention levels -> fp16 ====================
__global__ void cvt_sum_kernel() {
    int i = blockIdx.x * 256 + threadIdx.x;
    float4 a = ((const float4*)g_attn3[0])[i];
    float4 b = ((const float4*)g_attn3[1])[i];
    float4 c = ((const float4*)g_attn3[2])[i];
    __half2* hp = (__half2*)g_ahi + 2 * i;
    hp[0] = __floats2half2_rn(a.x + b.x + c.x, a.y + b.y + c.y);
    hp[1] = __floats2half2_rn(a.z + b.z + c.z, a.w + b.w + c.w);
}

// ==================== stable counting sort (keys 0..255, N=4096) ====================
// 256 threads, 16 contiguous elements each. cnt[thr][bin] u16 (128 KB dynamic smem).
// offset(k, thr) = prefix over (bins < k) + (same bin, threads < thr)  -> stable.
static constexpr int SORT_SMEM = 256 * 256 * 2;
__global__ __launch_bounds__(256) void sort_kernel(const int* __restrict__ wb0,
                                                   const int* __restrict__ wb1,
                                                   const int* __restrict__ wb2) {
    extern __shared__ __align__(4) unsigned short cnt[];   // [thr*256 + bin]
    __shared__ unsigned rowsum[256];
    __shared__ unsigned binbase[256];
    int batch = blockIdx.x, level = blockIdx.y;
    const int* wb = (level == 0) ? wb0 : (level == 1) ? wb1 : wb2;
    int t = threadIdx.x;

    // zero (bank-spread: thread t writes u32 elements t, t+256, ...)
    unsigned* c32 = (unsigned*)cnt;
#pragma unroll
    for (int i = 0; i < 128; i++) c32[t + 256 * i] = 0;
    __syncthreads();

    // histogram own segment
    int keys[16];
    const int* src = wb + batch * N_ + t * 16;
#pragma unroll
    for (int i = 0; i < 16; i++) {
        int k = src[i];
        keys[i] = k;
        cnt[t * 256 + k]++;
    }
    __syncthreads();

    // within-bin prefix over threads (thread t owns bin t; 2-way bank conflicts)
    unsigned run = 0;
    for (int r = 0; r < 256; r++) {
        unsigned v = cnt[r * 256 + t];
        cnt[r * 256 + t] = (unsigned short)run;
        run += v;
    }
    unsigned orig = run;
    rowsum[t] = run;
    __syncthreads();

    // Hillis-Steele inclusive scan over bin totals
    for (int ofs = 1; ofs < 256; ofs <<= 1) {
        unsigned yv = (t >= ofs) ? rowsum[t - ofs] : 0;
        __syncthreads();
        rowsum[t] += yv;
        __syncthreads();
    }
    binbase[t] = rowsum[t] - orig;     // exclusive prefix of bin t
    __syncthreads();

    // stable scatter (base folded in here; cnt row is private to this thread)
    int* dst = &g_sidx[level][batch][0];
#pragma unroll
    for (int i = 0; i < 16; i++) {
        int k = keys[i];
        unsigned c0 = cnt[t * 256 + k];
        cnt[t * 256 + k] = (unsigned short)(c0 + 1);
        dst[c0 + binbase[k]] = t * 16 + i;
    }
}

// ==================== HMMA fp16 2-product GEMM (unchanged, proven) ====================
static constexpr int TILEB = 128 * 128;
static constexpr int BUFB  = 3 * TILEB;
static constexpr int GEMM_SMEM = 2 * BUFB;              // 96KB

__global__ __launch_bounds__(512, 1) void gemm_tc(int qkv_mode,
                                                  const float* __restrict__ bias0,
                                                  const float* __restrict__ bias1,
                                                  const float* __restrict__ bias2,
                                                  float* __restrict__ out_ext) {
    extern __shared__ __align__(16) char dsm[];
    int z = blockIdx.z;
    const __half *Ah, *Bh, *Bl;
    const float* bias;
    if (qkv_mode) {
        Ah = g_xhi; Bh = g_whi[z]; Bl = g_wlo[z];
        bias = (z == 0) ? bias0 : (z == 1) ? bias1 : bias2;
    } else {
        Ah = g_ahi; Bh = g_whi[3]; Bl = g_wlo[3];
        bias = bias0;
    }

    int tid = threadIdx.x;
    int wid = tid >> 5, lane = tid & 31;
    int g = lane >> 2, t = lane & 3;
    int wm = wid >> 2, wn = wid & 3;
    int m0 = blockIdx.x * 128, n0 = blockIdx.y * 128;

    uint32_t sbase = smem_u32(dsm);
    const __half* srcs[3] = {
        Ah + (size_t)m0 * E_, Bh + (size_t)n0 * E_, Bl + (size_t)n0 * E_ };

    int lc = tid & 7, r6 = (tid >> 3) & 63;
    uint32_t cbyte = (uint32_t)(lc * 16);
    auto load_chunk = [&](int b, int kc) {
#pragma unroll
        for (int tgt = 0; tgt < 3; tgt++) {
            uint32_t tb = sbase + b * BUFB + tgt * TILEB;
            const __half* s = srcs[tgt] + kc * 64 + lc * 8;
#pragma unroll
            for (int p = 0; p < 2; p++) {
                int row = p * 64 + r6;
                cp16(tb + row * 128 + (cbyte ^ ((uint32_t)(row & 7) << 4)),
                     s + (size_t)row * E_);
            }
        }
        CP_COMMIT();
    };

    int lane7 = lane & 7, st = lane >> 3;
    int arow = wm * 32 + (st & 1) * 8 + lane7;
    uint32_t acolst = (uint32_t)((st >> 1) * 16);
    int brow = wn * 32 + (st >> 1) * 8 + lane7;
    uint32_t bcolst = (uint32_t)((st & 1) * 16);

    float acc[2][4][4];
#pragma unroll
    for (int i = 0; i < 2; i++)
#pragma unroll
        for (int j = 0; j < 4; j++)
#pragma unroll
            for (int q = 0; q < 4; q++) acc[i][j][q] = 0.f;

    load_chunk(0, 0);

    for (int kc = 0; kc < 16; kc++) {
        int b = kc & 1;
        if (kc + 1 < 16) { load_chunk(b ^ 1, kc + 1); CP_WAIT(1); }
        else             { CP_WAIT(0); }
        __syncthreads();

        uint32_t tA  = sbase + b * BUFB;
        uint32_t tB  = tA + TILEB;
        uint32_t tBl = tA + 2 * TILEB;

#pragma unroll
        for (int ks = 0; ks < 4; ks++) {
            uint32_t ko2 = (uint32_t)(ks * 32);
            uint32_t ah[2][4], bh[2][4], bl[2][4];
#pragma unroll
            for (int mi = 0; mi < 2; mi++) {
                int row = arow + mi * 16;
                uint32_t off = (uint32_t)(row * 128) + ((ko2 + acolst) ^ ((uint32_t)(row & 7) << 4));
                ldsm4(tA + off, ah[mi]);
            }
#pragma unroll
            for (int nb = 0; nb < 2; nb++) {
                int row = brow + nb * 16;
                uint32_t off = (uint32_t)(row * 128) + ((ko2 + bcolst) ^ ((uint32_t)(row & 7) << 4));
                ldsm4(tB + off, bh[nb]);
                ldsm4(tBl + off, bl[nb]);
            }
#pragma unroll
            for (int mi = 0; mi < 2; mi++)
#pragma unroll
                for (int ni = 0; ni < 4; ni++) {
                    int nb = ni >> 1, hf = (ni & 1) * 2;
                    mma16816(acc[mi][ni], ah[mi], bh[nb][hf], bh[nb][hf + 1]);
                    mma16816(acc[mi][ni], ah[mi], bl[nb][hf], bl[nb][hf + 1]);
                }
        }
        __syncthreads();
    }

    if (qkv_mode) {
        __half* outh = (z == 0) ? g_qh : (z == 1) ? g_kh : g_vh;
        float scl = (z == 0) ? 0.125f : 1.0f;
#pragma unroll
        for (int mi = 0; mi < 2; mi++) {
            int r0 = m0 + wm * 32 + mi * 16 + g;
#pragma unroll
            for (int ni = 0; ni < 4; ni++) {
                int col = n0 + wn * 32 + ni * 8 + 2 * t;
                float bx = bias[col], by = bias[col + 1];
                *(__half2*)(outh + (size_t)r0 * E_ + col) =
                    __floats2half2_rn((acc[mi][ni][0] + bx) * scl, (acc[mi][ni][1] + by) * scl);
                *(__half2*)(outh + (size_t)(r0 + 8) * E_ + col) =
                    __floats2half2_rn((acc[mi][ni][2] + bx) * scl, (acc[mi][ni][3] + by) * scl);
            }
        }
    } else {
        float* out = out_ext;
#pragma unroll
        for (int mi = 0; mi < 2; mi++) {
            int r0 = m0 + wm * 32 + mi * 16 + g;
#pragma unroll
            for (int ni = 0; ni < 4; ni++) {
                int col = n0 + wn * 32 + ni * 8 + 2 * t;
                float bx = bias[col], by = bias[col + 1];
                float2 v0 = { acc[mi][ni][0] + bx, acc[mi][ni][1] + by };
                float2 v1 = { acc[mi][ni][2] + bx, acc[mi][ni][3] + by };
                *(float2*)(out + (size_t)r0 * E_ + col) = v0;
                *(float2*)(out + (size_t)(r0 + 8) * E_ + col) = v1;
            }
        }
    }
}

// ==================== fused flash-MMA attention: 128-query blocks, 8 warps ====================
// grid (BH, N/128, 3); per-warp 16-query slice with per-warp key window + fragment masking.
__global__ __launch_bounds__(256) void attn_mma() {
    __shared__ __align__(16) __half sQ[128 * 64];
    __shared__ __align__(16) __half sK[2][64 * 64];
    __shared__ __align__(16) __half sV[2][64 * 64];

    int bh = blockIdx.x;
    int batch = bh >> 4, h = bh & 15;
    int qt = blockIdx.y;
    int level = blockIdx.z;
    const int* sidx = &g_sidx[level][batch][0];
    int tid = threadIdx.x, wid = tid >> 5, lane = tid & 31;
    int g = lane >> 2, t = lane & 3;

    int C = (level == 0) ? 256 : (level == 1) ? 64 : 16;
    int q0 = qt * 128;
    int cg0 = q0 / C, cgL = (q0 + 127) / C;
    int klo = cg0 ? (cg0 - 1) * C : 0;
    int khi = (cgL + 1) * C;
    int ntiles = (khi - klo + 63) >> 6;
    int cg = (q0 + wid * 16) / C;               // this warp's query chunk
    int wlo = cg ? (cg - 1) * C : 0;
    int whi = (cg + 1) * C;

    int fc = tid & 7, fr = tid >> 3;            // fr in [0,32)
    uint32_t fcb = (uint32_t)(fc * 16);
    size_t hbase = (size_t)(batch * N_) * E_ + h * HD_;
    uint32_t sq = smem_u32(sQ);
    uint32_t skb[2] = { smem_u32(sK[0]), smem_u32(sK[1]) };
    uint32_t svb[2] = { smem_u32(sV[0]), smem_u32(sV[1]) };

    auto load_kv = [&](int buf, int tile) {
#pragma unroll
        for (int p = 0; p < 2; p++) {
            int row = p * 32 + fr;
            int pos = klo + tile * 64 + row;
            int tok = sidx[min(pos, N_ - 1)];   // tail positions are masked later
            uint32_t off = (uint32_t)(row * 128) + (fcb ^ ((uint32_t)(row & 7) << 4));
            cp16(skb[buf] + off, (const uint4*)(g_kh + hbase + (size_t)tok * E_) + fc);
            cp16(svb[buf] + off, (const uint4*)(g_vh + hbase + (size_t)tok * E_) + fc);
        }
        CP_COMMIT();
    };

    // prefetch Q (128 rows) + KV tile 0 in one group
#pragma unroll
    for (int p = 0; p < 4; p++) {
        int row = p * 32 + fr;
        int tok = sidx[q0 + row];
        uint32_t off = (uint32_t)(row * 128) + (fcb ^ ((uint32_t)(row & 7) << 4));
        cp16(sq + off, (const uint4*)(g_qh + hbase + (size_t)tok * E_) + fc);
    }
    load_kv(0, 0);

    int lane7 = lane & 7, st = lane >> 3;
    int kbrow = (st >> 1) * 8 + lane7;
    uint32_t kbcol = (uint32_t)((st & 1) * 16);
    int vrow = (st & 1) * 8 + lane7;
    uint32_t vcol = (uint32_t)((lane >> 4) * 16);

    uint32_t aq[4][4];
    float o[8][4];
#pragma unroll
    for (int i = 0; i < 8; i++)
#pragma unroll
        for (int j = 0; j < 4; j++) o[i][j] = 0.f;
    float m0 = -1e30f, m1 = -1e30f, l0 = 0.f, l1 = 0.f;

    for (int tile = 0; tile < ntiles; tile++) {
        int buf = tile & 1;
        CP_WAIT(0);
        __syncthreads();
        if (tile == 0) {
            int arow = wid * 16 + (st & 1) * 8 + lane7;
            uint32_t acol = (uint32_t)((st >> 1) * 16);
#pragma unroll
            for (int kk = 0; kk < 4; kk++) {
                uint32_t off = (uint32_t)(arow * 128) + ((acol + kk * 32) ^ ((uint32_t)(arow & 7) << 4));
                ldsm4(sq + off, aq[kk]);
            }
        }
        if (tile + 1 < ntiles) load_kv(buf ^ 1, tile + 1);

        int tlo = klo + tile * 64;
        bool active = (wlo < tlo + 64) && (whi > tlo);
        bool partial = (wlo > tlo) || (whi < tlo + 64);
        if (active) {
            uint32_t sk = skb[buf], sv = svb[buf];
            float c[8][4];
#pragma unroll
            for (int i = 0; i < 8; i++)
#pragma unroll
                for (int j = 0; j < 4; j++) c[i][j] = 0.f;
#pragma unroll
            for (int kk = 0; kk < 4; kk++) {
                uint32_t ko2 = (uint32_t)(kk * 32);
#pragma unroll
                for (int nt = 0; nt < 4; nt++) {
                    int row = nt * 16 + kbrow;
                    uint32_t off = (uint32_t)(row * 128) + ((ko2 + kbcol) ^ ((uint32_t)(row & 7) << 4));
                    uint32_t bf[4];
                    ldsm4(sk + off, bf);
                    mma16816(c[2 * nt],     aq[kk], bf[0], bf[1]);
                    mma16816(c[2 * nt + 1], aq[kk], bf[2], bf[3]);
                }
            }
            if (partial) {
#pragma unroll
                for (int nt = 0; nt < 8; nt++) {
                    int col0 = tlo + nt * 8 + 2 * t;
                    if (col0 < wlo || col0 >= whi)         { c[nt][0] = -1e30f; c[nt][2] = -1e30f; }
                    if (col0 + 1 < wlo || col0 + 1 >= whi) { c[nt][1] = -1e30f; c[nt][3] = -1e30f; }
                }
            }
            float mx0 = -1e30f, mx1 = -1e30f;
#pragma unroll
            for (int nt = 0; nt < 8; nt++) {
                mx0 = fmaxf(mx0, fmaxf(c[nt][0], c[nt][1]));
                mx1 = fmaxf(mx1, fmaxf(c[nt][2], c[nt][3]));
            }
            mx0 = fmaxf(mx0, __shfl_xor_sync(0xFFFFFFFFu, mx0, 1));
            mx0 = fmaxf(mx0, __shfl_xor_sync(0xFFFFFFFFu, mx0, 2));
            mx1 = fmaxf(mx1, __shfl_xor_sync(0xFFFFFFFFu, mx1, 1));
            mx1 = fmaxf(mx1, __shfl_xor_sync(0xFFFFFFFFu, mx1, 2));
            float mn0 = fmaxf(m0, mx0), mn1 = fmaxf(m1, mx1);
            float cr0 = __expf(m0 - mn0), cr1 = __expf(m1 - mn1);
            m0 = mn0; m1 = mn1;
            l0 *= cr0; l1 *= cr1;
            uint32_t pA[8], pB[8];
#pragma unroll
            for (int nt = 0; nt < 8; nt++) {
                float e0 = __expf(c[nt][0] - m0), e1 = __expf(c[nt][1] - m0);
                float e2 = __expf(c[nt][2] - m1), e3 = __expf(c[nt][3] - m1);
                l0 += e0 + e1; l1 += e2 + e3;
                pA[nt] = packh2(e0, e1);
                pB[nt] = packh2(e2, e3);
            }
#pragma unroll
            for (int ht = 0; ht < 8; ht++) {
                o[ht][0] *= cr0; o[ht][1] *= cr0;
                o[ht][2] *= cr1; o[ht][3] *= cr1;
            }
#pragma unroll
            for (int kj = 0; kj < 4; kj++) {
                uint32_t a[4] = { pA[2 * kj], pB[2 * kj], pA[2 * kj + 1], pB[2 * kj + 1] };
#pragma unroll
                for (int ht = 0; ht < 4; ht++) {
                    int row = kj * 16 + vrow;
                    uint32_t off = (uint32_t)(row * 128) +
                                   (((uint32_t)(ht * 32) + vcol) ^ ((uint32_t)(row & 7) << 4));
                    uint32_t b[4];
                    ldsm4t(sv + off, b);
                    mma16816(o[2 * ht],     a, b[0], b[1]);
                    mma16816(o[2 * ht + 1], a, b[2], b[3]);
                }
            }
        }
        __syncthreads();
    }

    l0 += __shfl_xor_sync(0xFFFFFFFFu, l0, 1);
    l0 += __shfl_xor_sync(0xFFFFFFFFu, l0, 2);
    l1 += __shfl_xor_sync(0xFFFFFFFFu, l1, 1);
    l1 += __shfl_xor_sync(0xFFFFFFFFu, l1, 2);
    float inv0 = 1.f / (3.f * l0);
    float inv1 = 1.f / (3.f * l1);

    int pq0 = q0 + wid * 16 + g;
    int tok0 = sidx[pq0];
    int tok1 = sidx[pq0 + 8];
    float* base = g_attn3[level];
    float* d0 = base + (size_t)(batch * N_ + tok0) * E_ + h * HD_;
    float* d1 = base + (size_t)(batch * N_ + tok1) * E_ + h * HD_;
#pragma unroll
    for (int nt = 0; nt < 8; nt++) {
        int col = nt * 8 + 2 * t;
        float2 v0 = { o[nt][0] * inv0, o[nt][1] * inv0 };
        float2 v1 = { o[nt][2] * inv1, o[nt][3] * inv1 };
        *(float2*)(d0 + col) = v0;
        *(float2*)(d1 + col) = v1;
    }
}

// ==================== launch ====================
extern "C" void kernel_launch(void* const* d_in, const int* in_sizes, int n_in,
                              void* d_out, int out_size) {
    (void)in_sizes; (void)n_in; (void)out_size;
    const float* x   = (const float*)d_in[0];
    const int*   wbc = (const int*)d_in[1];
    const int*   wbm = (const int*)d_in[2];
    const int*   wbf = (const int*)d_in[3];
    const float* Wp[4] = { (const float*)d_in[4],  (const float*)d_in[8],
                           (const float*)d_in[12], (const float*)d_in[16] };
    const float* bp[4] = { (const float*)d_in[5],  (const float*)d_in[9],
                           (const float*)d_in[13], (const float*)d_in[17] };
    const float* Ap[4] = { (const float*)d_in[6],  (const float*)d_in[10],
                           (const float*)d_in[14], (const float*)d_in[18] };
    const float* Lp[4] = { (const float*)d_in[7],  (const float*)d_in[11],
                           (const float*)d_in[15], (const float*)d_in[19] };
    float* out = (float*)d_out;

    cudaFuncSetAttribute(gemm_tc, cudaFuncAttributeMaxDynamicSharedMemorySize, GEMM_SMEM);
    cudaFuncSetAttribute(sort_kernel, cudaFuncAttributeMaxDynamicSharedMemorySize, SORT_SMEM);

    // 1) fused LoRA fold + x->fp16
    prep_kernel<<<dim3(4096, 6), 256>>>(
        Wp[0], Ap[0], Lp[0], Wp[1], Ap[1], Lp[1],
        Wp[2], Ap[2], Lp[2], Wp[3], Ap[3], Lp[3], x);

    // 2) fused q,k,v projections -> fp16 (q pre-scaled by 1/8)
    gemm_tc<<<dim3(M_ / 128, E_ / 128, 3), 512, GEMM_SMEM>>>(1, bp[0], bp[1], bp[2], nullptr);

    // 3) stable counting sort per (batch, level)
    sort_kernel<<<dim3(B_, 3), 256, SORT_SMEM>>>(wbc, wbm, wbf);

    // 4) fused three-level flash-MMA attention (128-query blocks)
    attn_mma<<<dim3(BH_, N_ / 128, 3), 256>>>();

    // 5) sum levels + convert to fp16
    cvt_sum_kernel<<<(MSZ / 4) / 256, 256>>>();

    // 6) output projection
    gemm_tc<<<dim3(M_ / 128, E_ / 128, 1), 512, GEMM_SMEM>>>(0, bp[3], nullptr, nullptr, out);
}

// round 10
// speedup vs baseline: 5.3068x; 1.2014x over previous
#include <cuda_runtime.h>
#include <cuda_fp16.h>
#include <math.h>
#include <stdint.h>

#define B_   2
#define N_   4096
#define E_   1024
#define H_   16
#define HD_  64
#define BH_  32
#define M_   8192
#define MSZ  (M_ * E_)

// ==================== device scratch ====================
__device__ __align__(16) __half g_whi[4][E_ * E_];
__device__ __align__(16) __half g_wlo[4][E_ * E_];
__device__ __align__(16) __half g_xhi[MSZ];       // fp16(x)
__device__ __align__(16) __half g_ahi[MSZ];       // fp16(attn out, summed)
__device__ __align__(16) __half g_qh[MSZ];        // fp16 q (pre-scaled by 0.125*log2e)
__device__ __align__(16) __half g_kh[MSZ];
__device__ __align__(16) __half g_vh[MSZ];
__device__ __align__(16) float g_attn3[3][MSZ];   // per-level attention outputs
__device__ int g_sidx[3][B_][N_];

// ==================== helpers ====================
__device__ __forceinline__ uint32_t smem_u32(const void* p) {
    uint32_t a;
    asm("{ .reg .u64 t; cvta.to.shared.u64 t, %1; cvt.u32.u64 %0, t; }" : "=r"(a) : "l"(p));
    return a;
}
__device__ __forceinline__ void cp16(uint32_t dst, const void* src) {
    asm volatile("cp.async.cg.shared.global [%0], [%1], 16;" :: "r"(dst), "l"(src));
}
#define CP_COMMIT() asm volatile("cp.async.commit_group;" ::: "memory")
#define CP_WAIT(n)  asm volatile("cp.async.wait_group %0;" :: "n"(n) : "memory")

__device__ __forceinline__ void mma16816(float* c, const uint32_t* a, uint32_t b0, uint32_t b1) {
    asm volatile(
        "mma.sync.aligned.m16n8k16.row.col.f32.f16.f16.f32 "
        "{%0,%1,%2,%3}, {%4,%5,%6,%7}, {%8,%9}, {%0,%1,%2,%3};"
        : "+f"(c[0]), "+f"(c[1]), "+f"(c[2]), "+f"(c[3])
        : "r"(a[0]), "r"(a[1]), "r"(a[2]), "r"(a[3]), "r"(b0), "r"(b1));
}
__device__ __forceinline__ void ldsm4(uint32_t addr, uint32_t* r) {
    asm volatile("ldmatrix.sync.aligned.m8n8.x4.shared.b16 {%0,%1,%2,%3}, [%4];"
                 : "=r"(r[0]), "=r"(r[1]), "=r"(r[2]), "=r"(r[3]) : "r"(addr));
}
__device__ __forceinline__ void ldsm4t(uint32_t addr, uint32_t* r) {
    asm volatile("ldmatrix.sync.aligned.m8n8.x4.trans.shared.b16 {%0,%1,%2,%3}, [%4];"
                 : "=r"(r[0]), "=r"(r[1]), "=r"(r[2]), "=r"(r[3]) : "r"(addr));
}
__device__ __forceinline__ uint32_t packh2(float a, float b) {
    __half2 h = __floats2half2_rn(a, b);
    return *(uint32_t*)&h;
}

// ==================== fused prep: LoRA fold (y<4) + x->fp16 (y>=4) ====================
__global__ void prep_kernel(const float* __restrict__ W0, const float* __restrict__ A0, const float* __restrict__ B0,
                            const float* __restrict__ W1, const float* __restrict__ A1, const float* __restrict__ B1,
                            const float* __restrict__ W2, const float* __restrict__ A2, const float* __restrict__ B2,
                            const float* __restrict__ W3, const float* __restrict__ A3, const float* __restrict__ B3,
                            const float* __restrict__ x) {
    int y = blockIdx.y;
    if (y < 4) {
        const float* W = (y == 0) ? W0 : (y == 1) ? W1 : (y == 2) ? W2 : W3;
        const float* A = (y == 0) ? A0 : (y == 1) ? A1 : (y == 2) ? A2 : A3;
        const float* Bm = (y == 0) ? B0 : (y == 1) ? B1 : (y == 2) ? B2 : B3;
        int idx = blockIdx.x * 256 + threadIdx.x;
        int e = idx >> 10, k = idx & 1023;
        float acc = W[idx];
#pragma unroll
        for (int r = 0; r < 8; r++)
            acc = fmaf(2.0f * Bm[e * 8 + r], A[r * 1024 + k], acc);
        __half hi = __float2half_rn(acc);
        __half lo = __float2half_rn(acc - __half2float(hi));
        g_whi[y][idx] = hi;
        g_wlo[y][idx] = lo;
    } else {
        int i = (blockIdx.x + (y - 4) * 4096) * 256 + threadIdx.x;
        float4 v = ((const float4*)x)[i];
        __half2* hp = (__half2*)g_xhi + 2 * i;
        hp[0] = __floats2half2_rn(v.x, v.y);
        hp[1] = __floats2half2_rn(v.z, v.w);
    }
}

// ==================== sum 3 attention levels -> fp16 ====================
__global__ void cvt_sum_kernel() {
    int i = blockIdx.x * 256 + threadIdx.x;
    float4 a = ((const float4*)g_attn3[0])[i];
    float4 b = ((const float4*)g_attn3[1])[i];
    float4 c = ((const float4*)g_attn3[2])[i];
    __half2* hp = (__half2*)g_ahi + 2 * i;
    hp[0] = __floats2half2_rn(a.x + b.x + c.x, a.y + b.y + c.y);
    hp[1] = __floats2half2_rn(a.z + b.z + c.z, a.w + b.w + c.w);
}

// ==================== stable counting sort (keys 0..255, N=4096) ====================
static constexpr int SORT_SMEM = 256 * 256 * 2;
__global__ __launch_bounds__(256) void sort_kernel(const int* __restrict__ wb0,
                                                   const int* __restrict__ wb1,
                                                   const int* __restrict__ wb2) {
    extern __shared__ __align__(4) unsigned short cnt[];
    __shared__ unsigned rowsum[256];
    __shared__ unsigned binbase[256];
    int batch = blockIdx.x, level = blockIdx.y;
    const int* wb = (level == 0) ? wb0 : (level == 1) ? wb1 : wb2;
    int t = threadIdx.x;

    unsigned* c32 = (unsigned*)cnt;
#pragma unroll
    for (int i = 0; i < 128; i++) c32[t + 256 * i] = 0;
    __syncthreads();

    int keys[16];
    const int* src = wb + batch * N_ + t * 16;
#pragma unroll
    for (int i = 0; i < 16; i++) {
        int k = src[i];
        keys[i] = k;
        cnt[t * 256 + k]++;
    }
    __syncthreads();

    unsigned run = 0;
    for (int r = 0; r < 256; r++) {
        unsigned v = cnt[r * 256 + t];
        cnt[r * 256 + t] = (unsigned short)run;
        run += v;
    }
    unsigned orig = run;
    rowsum[t] = run;
    __syncthreads();

    for (int ofs = 1; ofs < 256; ofs <<= 1) {
        unsigned yv = (t >= ofs) ? rowsum[t - ofs] : 0;
        __syncthreads();
        rowsum[t] += yv;
        __syncthreads();
    }
    binbase[t] = rowsum[t] - orig;
    __syncthreads();

    int* dst = &g_sidx[level][batch][0];
#pragma unroll
    for (int i = 0; i < 16; i++) {
        int k = keys[i];
        unsigned c0 = cnt[t * 256 + k];
        cnt[t * 256 + k] = (unsigned short)(c0 + 1);
        dst[c0 + binbase[k]] = t * 16 + i;
    }
}

// ==================== HMMA fp16 2-product GEMM: 256 thr, 64x32 warp tiles, 2 CTA/SM ====================
static constexpr int TILEB = 128 * 128;
static constexpr int BUFB  = 3 * TILEB;
static constexpr int GEMM_SMEM = 2 * BUFB;              // 96KB

__global__ __launch_bounds__(256, 2) void gemm_tc(int qkv_mode,
                                                  const float* __restrict__ bias0,
                                                  const float* __restrict__ bias1,
                                                  const float* __restrict__ bias2,
                                                  float* __restrict__ out_ext) {
    extern __shared__ __align__(16) char dsm[];
    int z = blockIdx.z;
    const __half *Ah, *Bh, *Bl;
    const float* bias;
    if (qkv_mode) {
        Ah = g_xhi; Bh = g_whi[z]; Bl = g_wlo[z];
        bias = (z == 0) ? bias0 : (z == 1) ? bias1 : bias2;
    } else {
        Ah = g_ahi; Bh = g_whi[3]; Bl = g_wlo[3];
        bias = bias0;
    }

    int tid = threadIdx.x;
    int wid = tid >> 5, lane = tid & 31;
    int g = lane >> 2, t = lane & 3;
    int wm = wid >> 2, wn = wid & 3;                    // 2x4 warp grid, 64x32 tiles
    int m0 = blockIdx.x * 128, n0 = blockIdx.y * 128;

    uint32_t sbase = smem_u32(dsm);
    const __half* srcs[3] = {
        Ah + (size_t)m0 * E_, Bh + (size_t)n0 * E_, Bl + (size_t)n0 * E_ };

    // coalesced loader: 256 threads, 12 cp16 each per chunk
    int lc = tid & 7, r5 = (tid >> 3) & 31;
    uint32_t cbyte = (uint32_t)(lc * 16);
    auto load_chunk = [&](int b, int kc) {
#pragma unroll
        for (int tgt = 0; tgt < 3; tgt++) {
            uint32_t tb = sbase + b * BUFB + tgt * TILEB;
            const __half* s = srcs[tgt] + kc * 64 + lc * 8;
#pragma unroll
            for (int p = 0; p < 4; p++) {
                int row = p * 32 + r5;
                cp16(tb + row * 128 + (cbyte ^ ((uint32_t)(row & 7) << 4)),
                     s + (size_t)row * E_);
            }
        }
        CP_COMMIT();
    };

    int lane7 = lane & 7, st = lane >> 3;
    int arow = wm * 64 + (st & 1) * 8 + lane7;          // + mi*16
    uint32_t acolst = (uint32_t)((st >> 1) * 16);
    int brow = wn * 32 + (st >> 1) * 8 + lane7;         // + nb*16
    uint32_t bcolst = (uint32_t)((st & 1) * 16);

    float acc[4][4][4];
#pragma unroll
    for (int i = 0; i < 4; i++)
#pragma unroll
        for (int j = 0; j < 4; j++)
#pragma unroll
            for (int q = 0; q < 4; q++) acc[i][j][q] = 0.f;

    load_chunk(0, 0);

    for (int kc = 0; kc < 16; kc++) {
        int b = kc & 1;
        if (kc + 1 < 16) { load_chunk(b ^ 1, kc + 1); CP_WAIT(1); }
        else             { CP_WAIT(0); }
        __syncthreads();

        uint32_t tA  = sbase + b * BUFB;
        uint32_t tB  = tA + TILEB;
        uint32_t tBl = tA + 2 * TILEB;

#pragma unroll
        for (int ks = 0; ks < 4; ks++) {
            uint32_t ko2 = (uint32_t)(ks * 32);
            uint32_t ah[4][4], bh[2][4], bl[2][4];
#pragma unroll
            for (int mi = 0; mi < 4; mi++) {
                int row = arow + mi * 16;
                uint32_t off = (uint32_t)(row * 128) + ((ko2 + acolst) ^ ((uint32_t)(row & 7) << 4));
                ldsm4(tA + off, ah[mi]);
            }
#pragma unroll
            for (int nb = 0; nb < 2; nb++) {
                int row = brow + nb * 16;
                uint32_t off = (uint32_t)(row * 128) + ((ko2 + bcolst) ^ ((uint32_t)(row & 7) << 4));
                ldsm4(tB + off, bh[nb]);
                ldsm4(tBl + off, bl[nb]);
            }
#pragma unroll
            for (int mi = 0; mi < 4; mi++)
#pragma unroll
                for (int ni = 0; ni < 4; ni++) {
                    int nb = ni >> 1, hf = (ni & 1) * 2;
                    mma16816(acc[mi][ni], ah[mi], bh[nb][hf], bh[nb][hf + 1]);
                    mma16816(acc[mi][ni], ah[mi], bl[nb][hf], bl[nb][hf + 1]);
                }
        }
        __syncthreads();
    }

    if (qkv_mode) {
        __half* outh = (z == 0) ? g_qh : (z == 1) ? g_kh : g_vh;
        // q pre-scale: 1/sqrt(64) * log2(e)  (attention uses exp2)
        float scl = (z == 0) ? 0.125f * 1.4426950408889634f : 1.0f;
#pragma unroll
        for (int mi = 0; mi < 4; mi++) {
            int r0 = m0 + wm * 64 + mi * 16 + g;
#pragma unroll
            for (int ni = 0; ni < 4; ni++) {
                int col = n0 + wn * 32 + ni * 8 + 2 * t;
                float bx = bias[col], by = bias[col + 1];
                *(__half2*)(outh + (size_t)r0 * E_ + col) =
                    __floats2half2_rn((acc[mi][ni][0] + bx) * scl, (acc[mi][ni][1] + by) * scl);
                *(__half2*)(outh + (size_t)(r0 + 8) * E_ + col) =
                    __floats2half2_rn((acc[mi][ni][2] + bx) * scl, (acc[mi][ni][3] + by) * scl);
            }
        }
    } else {
        float* out = out_ext;
#pragma unroll
        for (int mi = 0; mi < 4; mi++) {
            int r0 = m0 + wm * 64 + mi * 16 + g;
#pragma unroll
            for (int ni = 0; ni < 4; ni++) {
                int col = n0 + wn * 32 + ni * 8 + 2 * t;
                float bx = bias[col], by = bias[col + 1];
                float2 v0 = { acc[mi][ni][0] + bx, acc[mi][ni][1] + by };
                float2 v1 = { acc[mi][ni][2] + bx, acc[mi][ni][3] + by };
                *(float2*)(out + (size_t)r0 * E_ + col) = v0;
                *(float2*)(out + (size_t)(r0 + 8) * E_ + col) = v1;
            }
        }
    }
}

// ==================== fused flash-MMA attention: 128-query blocks, 8 warps ====================
__global__ __launch_bounds__(256) void attn_mma() {
    __shared__ __align__(16) __half sQ[128 * 64];
    __shared__ __align__(16) __half sK[2][64 * 64];
    __shared__ __align__(16) __half sV[2][64 * 64];

    int bh = blockIdx.x;
    int batch = bh >> 4, h = bh & 15;
    int qt = blockIdx.y;
    int level = blockIdx.z;
    const int* sidx = &g_sidx[level][batch][0];
    int tid = threadIdx.x, wid = tid >> 5, lane = tid & 31;
    int g = lane >> 2, t = lane & 3;

    int C = (level == 0) ? 256 : (level == 1) ? 64 : 16;
    int q0 = qt * 128;
    int cg0 = q0 / C, cgL = (q0 + 127) / C;
    int klo = cg0 ? (cg0 - 1) * C : 0;
    int khi = (cgL + 1) * C;
    int ntiles = (khi - klo + 63) >> 6;
    int cg = (q0 + wid * 16) / C;
    int wlo = cg ? (cg - 1) * C : 0;
    int whi = (cg + 1) * C;

    int fc = tid & 7, fr = tid >> 3;
    uint32_t fcb = (uint32_t)(fc * 16);
    size_t hbase = (size_t)(batch * N_) * E_ + h * HD_;
    uint32_t sq = smem_u32(sQ);
    uint32_t skb[2] = { smem_u32(sK[0]), smem_u32(sK[1]) };
    uint32_t svb[2] = { smem_u32(sV[0]), smem_u32(sV[1]) };

    auto load_kv = [&](int buf, int tile) {
#pragma unroll
        for (int p = 0; p < 2; p++) {
            int row = p * 32 + fr;
            int pos = klo + tile * 64 + row;
            int tok = sidx[min(pos, N_ - 1)];
            uint32_t off = (uint32_t)(row * 128) + (fcb ^ ((uint32_t)(row & 7) << 4));
            cp16(skb[buf] + off, (const uint4*)(g_kh + hbase + (size_t)tok * E_) + fc);
            cp16(svb[buf] + off, (const uint4*)(g_vh + hbase + (size_t)tok * E_) + fc);
        }
        CP_COMMIT();
    };

#pragma unroll
    for (int p = 0; p < 4; p++) {
        int row = p * 32 + fr;
        int tok = sidx[q0 + row];
        uint32_t off = (uint32_t)(row * 128) + (fcb ^ ((uint32_t)(row & 7) << 4));
        cp16(sq + off, (const uint4*)(g_qh + hbase + (size_t)tok * E_) + fc);
    }
    load_kv(0, 0);

    int lane7 = lane & 7, st = lane >> 3;
    int kbrow = (st >> 1) * 8 + lane7;
    uint32_t kbcol = (uint32_t)((st & 1) * 16);
    int vrow = (st & 1) * 8 + lane7;
    uint32_t vcol = (uint32_t)((lane >> 4) * 16);

    uint32_t aq[4][4];
    float o[8][4];
#pragma unroll
    for (int i = 0; i < 8; i++)
#pragma unroll
        for (int j = 0; j < 4; j++) o[i][j] = 0.f;
    float m0 = -1e30f, m1 = -1e30f, l0 = 0.f, l1 = 0.f;

    for (int tile = 0; tile < ntiles; tile++) {
        int buf = tile & 1;
        CP_WAIT(0);
        __syncthreads();
        if (tile == 0) {
            int arow = wid * 16 + (st & 1) * 8 + lane7;
            uint32_t acol = (uint32_t)((st >> 1) * 16);
#pragma unroll
            for (int kk = 0; kk < 4; kk++) {
                uint32_t off = (uint32_t)(arow * 128) + ((acol + kk * 32) ^ ((uint32_t)(arow & 7) << 4));
                ldsm4(sq + off, aq[kk]);
            }
        }
        if (tile + 1 < ntiles) load_kv(buf ^ 1, tile + 1);

        int tlo = klo + tile * 64;
        bool active = (wlo < tlo + 64) && (whi > tlo);
        bool partial = (wlo > tlo) || (whi < tlo + 64);
        if (active) {
            uint32_t sk = skb[buf], sv = svb[buf];
            float c[8][4];
#pragma unroll
            for (int i = 0; i < 8; i++)
#pragma unroll
                for (int j = 0; j < 4; j++) c[i][j] = 0.f;
#pragma unroll
            for (int kk = 0; kk < 4; kk++) {
                uint32_t ko2 = (uint32_t)(kk * 32);
#pragma unroll
                for (int nt = 0; nt < 4; nt++) {
                    int row = nt * 16 + kbrow;
                    uint32_t off = (uint32_t)(row * 128) + ((ko2 + kbcol) ^ ((uint32_t)(row & 7) << 4));
                    uint32_t bf[4];
                    ldsm4(sk + off, bf);
                    mma16816(c[2 * nt],     aq[kk], bf[0], bf[1]);
                    mma16816(c[2 * nt + 1], aq[kk], bf[2], bf[3]);
                }
            }
            if (partial) {
#pragma unroll
                for (int nt = 0; nt < 8; nt++) {
                    int col0 = tlo + nt * 8 + 2 * t;
                    if (col0 < wlo || col0 >= whi)         { c[nt][0] = -1e30f; c[nt][2] = -1e30f; }
                    if (col0 + 1 < wlo || col0 + 1 >= whi) { c[nt][1] = -1e30f; c[nt][3] = -1e30f; }
                }
            }
            float mx0 = -1e30f, mx1 = -1e30f;
#pragma unroll
            for (int nt = 0; nt < 8; nt++) {
                mx0 = fmaxf(mx0, fmaxf(c[nt][0], c[nt][1]));
                mx1 = fmaxf(mx1, fmaxf(c[nt][2], c[nt][3]));
            }
            mx0 = fmaxf(mx0, __shfl_xor_sync(0xFFFFFFFFu, mx0, 1));
            mx0 = fmaxf(mx0, __shfl_xor_sync(0xFFFFFFFFu, mx0, 2));
            mx1 = fmaxf(mx1, __shfl_xor_sync(0xFFFFFFFFu, mx1, 1));
            mx1 = fmaxf(mx1, __shfl_xor_sync(0xFFFFFFFFu, mx1, 2));
            float mn0 = fmaxf(m0, mx0), mn1 = fmaxf(m1, mx1);
            float cr0 = exp2f(m0 - mn0), cr1 = exp2f(m1 - mn1);
            m0 = mn0; m1 = mn1;
            l0 *= cr0; l1 *= cr1;
            uint32_t pA[8], pB[8];
#pragma unroll
            for (int nt = 0; nt < 8; nt++) {
                float e0 = exp2f(c[nt][0] - m0), e1 = exp2f(c[nt][1] - m0);
                float e2 = exp2f(c[nt][2] - m1), e3 = exp2f(c[nt][3] - m1);
                l0 += e0 + e1; l1 += e2 + e3;
                pA[nt] = packh2(e0, e1);
                pB[nt] = packh2(e2, e3);
            }
#pragma unroll
            for (int ht = 0; ht < 8; ht++) {
                o[ht][0] *= cr0; o[ht][1] *= cr0;
                o[ht][2] *= cr1; o[ht][3] *= cr1;
            }
#pragma unroll
            for (int kj = 0; kj < 4; kj++) {
                uint32_t a[4] = { pA[2 * kj], pB[2 * kj], pA[2 * kj + 1], pB[2 * kj + 1] };
#pragma unroll
                for (int ht = 0; ht < 4; ht++) {
                    int row = kj * 16 + vrow;
                    uint32_t off = (uint32_t)(row * 128) +
                                   (((uint32_t)(ht * 32) + vcol) ^ ((uint32_t)(row & 7) << 4));
                    uint32_t b[4];
                    ldsm4t(sv + off, b);
                    mma16816(o[2 * ht],     a, b[0], b[1]);
                    mma16816(o[2 * ht + 1], a, b[2], b[3]);
                }
            }
        }
        __syncthreads();
    }

    l0 += __shfl_xor_sync(0xFFFFFFFFu, l0, 1);
    l0 += __shfl_xor_sync(0xFFFFFFFFu, l0, 2);
    l1 += __shfl_xor_sync(0xFFFFFFFFu, l1, 1);
    l1 += __shfl_xor_sync(0xFFFFFFFFu, l1, 2);
    float inv0 = 1.f / (3.f * l0);
    float inv1 = 1.f / (3.f * l1);

    int pq0 = q0 + wid * 16 + g;
    int tok0 = sidx[pq0];
    int tok1 = sidx[pq0 + 8];
    float* base = g_attn3[level];
    float* d0 = base + (size_t)(batch * N_ + tok0) * E_ + h * HD_;
    float* d1 = base + (size_t)(batch * N_ + tok1) * E_ + h * HD_;
#pragma unroll
    for (int nt = 0; nt < 8; nt++) {
        int col = nt * 8 + 2 * t;
        float2 v0 = { o[nt][0] * inv0, o[nt][1] * inv0 };
        float2 v1 = { o[nt][2] * inv1, o[nt][3] * inv1 };
        *(float2*)(d0 + col) = v0;
        *(float2*)(d1 + col) = v1;
    }
}

// ==================== launch ====================
extern "C" void kernel_launch(void* const* d_in, const int* in_sizes, int n_in,
                              void* d_out, int out_size) {
    (void)in_sizes; (void)n_in; (void)out_size;
    const float* x   = (const float*)d_in[0];
    const int*   wbc = (const int*)d_in[1];
    const int*   wbm = (const int*)d_in[2];
    const int*   wbf = (const int*)d_in[3];
    const float* Wp[4] = { (const float*)d_in[4],  (const float*)d_in[8],
                           (const float*)d_in[12], (const float*)d_in[16] };
    const float* bp[4] = { (const float*)d_in[5],  (const float*)d_in[9],
                           (const float*)d_in[13], (const float*)d_in[17] };
    const float* Ap[4] = { (const float*)d_in[6],  (const float*)d_in[10],
                           (const float*)d_in[14], (const float*)d_in[18] };
    const float* Lp[4] = { (const float*)d_in[7],  (const float*)d_in[11],
                           (const float*)d_in[15], (const float*)d_in[19] };
    float* out = (float*)d_out;

    cudaFuncSetAttribute(gemm_tc, cudaFuncAttributeMaxDynamicSharedMemorySize, GEMM_SMEM);
    cudaFuncSetAttribute(sort_kernel, cudaFuncAttributeMaxDynamicSharedMemorySize, SORT_SMEM);

    // 1) fused LoRA fold + x->fp16
    prep_kernel<<<dim3(4096, 6), 256>>>(
        Wp[0], Ap[0], Lp[0], Wp[1], Ap[1], Lp[1],
        Wp[2], Ap[2], Lp[2], Wp[3], Ap[3], Lp[3], x);

    // 2) fused q,k,v projections -> fp16 (q pre-scaled by 0.125*log2e)
    gemm_tc<<<dim3(M_ / 128, E_ / 128, 3), 256, GEMM_SMEM>>>(1, bp[0], bp[1], bp[2], nullptr);

    // 3) stable counting sort per (batch, level)
    sort_kernel<<<dim3(B_, 3), 256, SORT_SMEM>>>(wbc, wbm, wbf);

    // 4) fused three-level flash-MMA attention (exp2 softmax)
    attn_mma<<<dim3(BH_, N_ / 128, 3), 256>>>();

    // 5) sum levels + convert to fp16
    cvt_sum_kernel<<<(MSZ / 4) / 256, 256>>>();

    // 6) output projection
    gemm_tc<<<dim3(M_ / 128, E_ / 128, 1), 256, GEMM_SMEM>>>(0, bp[3], nullptr, nullptr, out);
}

// round 11
// speedup vs baseline: 7.4919x; 1.4118x over previous
#include <cuda_runtime.h>
#include <cuda_fp16.h>
#include <math.h>
#include <stdint.h>

#define B_   2
#define N_   4096
#define E_   1024
#define H_   16
#define HD_  64
#define BH_  32
#define M_   8192
#define MSZ  (M_ * E_)

// ==================== device scratch ====================
__device__ __align__(16) __half g_wh[4][E_ * E_];   // fp16 folded weights
__device__ __align__(16) __half g_xhi[MSZ];         // fp16(x)
__device__ __align__(16) __half g_ahi[MSZ];         // fp16(attn out, summed)
__device__ __align__(16) __half g_qh[MSZ];          // fp16 q (pre-scaled by 0.125*log2e)
__device__ __align__(16) __half g_kh[MSZ];
__device__ __align__(16) __half g_vh[MSZ];
__device__ __align__(16) __half g_attn3[3][MSZ];    // per-level attention outputs (fp16)
__device__ int g_sidx[3][B_][N_];

// ==================== helpers ====================
__device__ __forceinline__ uint32_t smem_u32(const void* p) {
    uint32_t a;
    asm("{ .reg .u64 t; cvta.to.shared.u64 t, %1; cvt.u32.u64 %0, t; }" : "=r"(a) : "l"(p));
    return a;
}
__device__ __forceinline__ void cp16(uint32_t dst, const void* src) {
    asm volatile("cp.async.cg.shared.global [%0], [%1], 16;" :: "r"(dst), "l"(src));
}
#define CP_COMMIT() asm volatile("cp.async.commit_group;" ::: "memory")
#define CP_WAIT(n)  asm volatile("cp.async.wait_group %0;" :: "n"(n) : "memory")

__device__ __forceinline__ void mma16816(float* c, const uint32_t* a, uint32_t b0, uint32_t b1) {
    asm volatile(
        "mma.sync.aligned.m16n8k16.row.col.f32.f16.f16.f32 "
        "{%0,%1,%2,%3}, {%4,%5,%6,%7}, {%8,%9}, {%0,%1,%2,%3};"
        : "+f"(c[0]), "+f"(c[1]), "+f"(c[2]), "+f"(c[3])
        : "r"(a[0]), "r"(a[1]), "r"(a[2]), "r"(a[3]), "r"(b0), "r"(b1));
}
__device__ __forceinline__ void ldsm4(uint32_t addr, uint32_t* r) {
    asm volatile("ldmatrix.sync.aligned.m8n8.x4.shared.b16 {%0,%1,%2,%3}, [%4];"
                 : "=r"(r[0]), "=r"(r[1]), "=r"(r[2]), "=r"(r[3]) : "r"(addr));
}
__device__ __forceinline__ void ldsm4t(uint32_t addr, uint32_t* r) {
    asm volatile("ldmatrix.sync.aligned.m8n8.x4.trans.shared.b16 {%0,%1,%2,%3}, [%4];"
                 : "=r"(r[0]), "=r"(r[1]), "=r"(r[2]), "=r"(r[3]) : "r"(addr));
}
__device__ __forceinline__ uint32_t packh2(float a, float b) {
    __half2 h = __floats2half2_rn(a, b);
    return *(uint32_t*)&h;
}

// ==================== fused prep: LoRA fold -> fp16 (y<4) + x->fp16 (y>=4) ====================
__global__ void prep_kernel(const float* __restrict__ W0, const float* __restrict__ A0, const float* __restrict__ B0,
                            const float* __restrict__ W1, const float* __restrict__ A1, const float* __restrict__ B1,
                            const float* __restrict__ W2, const float* __restrict__ A2, const float* __restrict__ B2,
                            const float* __restrict__ W3, const float* __restrict__ A3, const float* __restrict__ B3,
                            const float* __restrict__ x) {
    int y = blockIdx.y;
    if (y < 4) {
        const float* W = (y == 0) ? W0 : (y == 1) ? W1 : (y == 2) ? W2 : W3;
        const float* A = (y == 0) ? A0 : (y == 1) ? A1 : (y == 2) ? A2 : A3;
        const float* Bm = (y == 0) ? B0 : (y == 1) ? B1 : (y == 2) ? B2 : B3;
        int idx = blockIdx.x * 256 + threadIdx.x;
        int e = idx >> 10, k = idx & 1023;
        float acc = W[idx];
#pragma unroll
        for (int r = 0; r < 8; r++)
            acc = fmaf(2.0f * Bm[e * 8 + r], A[r * 1024 + k], acc);
        g_wh[y][idx] = __float2half_rn(acc);
    } else {
        int i = (blockIdx.x + (y - 4) * 4096) * 256 + threadIdx.x;
        float4 v = ((const float4*)x)[i];
        __half2* hp = (__half2*)g_xhi + 2 * i;
        hp[0] = __floats2half2_rn(v.x, v.y);
        hp[1] = __floats2half2_rn(v.z, v.w);
    }
}

// ==================== sum 3 fp16 attention levels -> fp16 ====================
__global__ void cvt_sum_kernel() {
    int i = blockIdx.x * 256 + threadIdx.x;          // over MSZ/8 uint4-of-half8
    uint4 a = ((const uint4*)g_attn3[0])[i];
    uint4 b = ((const uint4*)g_attn3[1])[i];
    uint4 c = ((const uint4*)g_attn3[2])[i];
    uint4 r;
    const uint32_t* pa = &a.x;
    const uint32_t* pb = &b.x;
    const uint32_t* pc = &c.x;
    uint32_t* pr = &r.x;
#pragma unroll
    for (int j = 0; j < 4; j++) {
        float2 fa = __half22float2(*(const __half2*)&pa[j]);
        float2 fb = __half22float2(*(const __half2*)&pb[j]);
        float2 fc = __half22float2(*(const __half2*)&pc[j]);
        __half2 h = __floats2half2_rn(fa.x + fb.x + fc.x, fa.y + fb.y + fc.y);
        pr[j] = *(uint32_t*)&h;
    }
    ((uint4*)g_ahi)[i] = r;
}

// ==================== stable counting sort (keys 0..255, N=4096) ====================
static constexpr int SORT_SMEM = 256 * 256 * 2;
__global__ __launch_bounds__(256) void sort_kernel(const int* __restrict__ wb0,
                                                   const int* __restrict__ wb1,
                                                   const int* __restrict__ wb2) {
    extern __shared__ __align__(4) unsigned short cnt[];
    __shared__ unsigned rowsum[256];
    __shared__ unsigned binbase[256];
    int batch = blockIdx.x, level = blockIdx.y;
    const int* wb = (level == 0) ? wb0 : (level == 1) ? wb1 : wb2;
    int t = threadIdx.x;

    unsigned* c32 = (unsigned*)cnt;
#pragma unroll
    for (int i = 0; i < 128; i++) c32[t + 256 * i] = 0;
    __syncthreads();

    int keys[16];
    const int* src = wb + batch * N_ + t * 16;
#pragma unroll
    for (int i = 0; i < 16; i++) {
        int k = src[i];
        keys[i] = k;
        cnt[t * 256 + k]++;
    }
    __syncthreads();

    unsigned run = 0;
    for (int r = 0; r < 256; r++) {
        unsigned v = cnt[r * 256 + t];
        cnt[r * 256 + t] = (unsigned short)run;
        run += v;
    }
    unsigned orig = run;
    rowsum[t] = run;
    __syncthreads();

    for (int ofs = 1; ofs < 256; ofs <<= 1) {
        unsigned yv = (t >= ofs) ? rowsum[t - ofs] : 0;
        __syncthreads();
        rowsum[t] += yv;
        __syncthreads();
    }
    binbase[t] = rowsum[t] - orig;
    __syncthreads();

    int* dst = &g_sidx[level][batch][0];
#pragma unroll
    for (int i = 0; i < 16; i++) {
        int k = keys[i];
        unsigned c0 = cnt[t * 256 + k];
        cnt[t * 256 + k] = (unsigned short)(c0 + 1);
        dst[c0 + binbase[k]] = t * 16 + i;
    }
}

// ==================== HMMA fp16 single-product GEMM: 256 thr, 64x32 warp tiles ====================
static constexpr int TILEB = 128 * 128;
static constexpr int BUFB  = 2 * TILEB;                 // A | B = 32KB
static constexpr int GEMM_SMEM = 2 * BUFB;              // 64KB double-buffered

__global__ __launch_bounds__(256, 2) void gemm_tc(int qkv_mode,
                                                  const float* __restrict__ bias0,
                                                  const float* __restrict__ bias1,
                                                  const float* __restrict__ bias2,
                                                  float* __restrict__ out_ext) {
    extern __shared__ __align__(16) char dsm[];
    int z = blockIdx.z;
    const __half *Ah, *Bh;
    const float* bias;
    if (qkv_mode) {
        Ah = g_xhi; Bh = g_wh[z];
        bias = (z == 0) ? bias0 : (z == 1) ? bias1 : bias2;
    } else {
        Ah = g_ahi; Bh = g_wh[3];
        bias = bias0;
    }

    int tid = threadIdx.x;
    int wid = tid >> 5, lane = tid & 31;
    int g = lane >> 2, t = lane & 3;
    int wm = wid >> 2, wn = wid & 3;                    // 2x4 warp grid, 64x32 tiles
    int m0 = blockIdx.x * 128, n0 = blockIdx.y * 128;

    uint32_t sbase = smem_u32(dsm);
    const __half* srcs[2] = { Ah + (size_t)m0 * E_, Bh + (size_t)n0 * E_ };

    int lc = tid & 7, r5 = (tid >> 3) & 31;
    uint32_t cbyte = (uint32_t)(lc * 16);
    auto load_chunk = [&](int b, int kc) {
#pragma unroll
        for (int tgt = 0; tgt < 2; tgt++) {
            uint32_t tb = sbase + b * BUFB + tgt * TILEB;
            const __half* s = srcs[tgt] + kc * 64 + lc * 8;
#pragma unroll
            for (int p = 0; p < 4; p++) {
                int row = p * 32 + r5;
                cp16(tb + row * 128 + (cbyte ^ ((uint32_t)(row & 7) << 4)),
                     s + (size_t)row * E_);
            }
        }
        CP_COMMIT();
    };

    int lane7 = lane & 7, st = lane >> 3;
    int arow = wm * 64 + (st & 1) * 8 + lane7;          // + mi*16
    uint32_t acolst = (uint32_t)((st >> 1) * 16);
    int brow = wn * 32 + (st >> 1) * 8 + lane7;         // + nb*16
    uint32_t bcolst = (uint32_t)((st & 1) * 16);

    float acc[4][4][4];
#pragma unroll
    for (int i = 0; i < 4; i++)
#pragma unroll
        for (int j = 0; j < 4; j++)
#pragma unroll
            for (int q = 0; q < 4; q++) acc[i][j][q] = 0.f;

    load_chunk(0, 0);

    for (int kc = 0; kc < 16; kc++) {
        int b = kc & 1;
        if (kc + 1 < 16) { load_chunk(b ^ 1, kc + 1); CP_WAIT(1); }
        else             { CP_WAIT(0); }
        __syncthreads();

        uint32_t tA = sbase + b * BUFB;
        uint32_t tB = tA + TILEB;

#pragma unroll
        for (int ks = 0; ks < 4; ks++) {
            uint32_t ko2 = (uint32_t)(ks * 32);
            uint32_t ah[4][4], bh[2][4];
#pragma unroll
            for (int mi = 0; mi < 4; mi++) {
                int row = arow + mi * 16;
                uint32_t off = (uint32_t)(row * 128) + ((ko2 + acolst) ^ ((uint32_t)(row & 7) << 4));
                ldsm4(tA + off, ah[mi]);
            }
#pragma unroll
            for (int nb = 0; nb < 2; nb++) {
                int row = brow + nb * 16;
                uint32_t off = (uint32_t)(row * 128) + ((ko2 + bcolst) ^ ((uint32_t)(row & 7) << 4));
                ldsm4(tB + off, bh[nb]);
            }
#pragma unroll
            for (int mi = 0; mi < 4; mi++)
#pragma unroll
                for (int ni = 0; ni < 4; ni++) {
                    int nb = ni >> 1, hf = (ni & 1) * 2;
                    mma16816(acc[mi][ni], ah[mi], bh[nb][hf], bh[nb][hf + 1]);
                }
        }
        __syncthreads();
    }

    if (qkv_mode) {
        __half* outh = (z == 0) ? g_qh : (z == 1) ? g_kh : g_vh;
        float scl = (z == 0) ? 0.125f * 1.4426950408889634f : 1.0f;
#pragma unroll
        for (int mi = 0; mi < 4; mi++) {
            int r0 = m0 + wm * 64 + mi * 16 + g;
#pragma unroll
            for (int ni = 0; ni < 4; ni++) {
                int col = n0 + wn * 32 + ni * 8 + 2 * t;
                float bx = bias[col], by = bias[col + 1];
                *(__half2*)(outh + (size_t)r0 * E_ + col) =
                    __floats2half2_rn((acc[mi][ni][0] + bx) * scl, (acc[mi][ni][1] + by) * scl);
                *(__half2*)(outh + (size_t)(r0 + 8) * E_ + col) =
                    __floats2half2_rn((acc[mi][ni][2] + bx) * scl, (acc[mi][ni][3] + by) * scl);
            }
        }
    } else {
        float* out = out_ext;
#pragma unroll
        for (int mi = 0; mi < 4; mi++) {
            int r0 = m0 + wm * 64 + mi * 16 + g;
#pragma unroll
            for (int ni = 0; ni < 4; ni++) {
                int col = n0 + wn * 32 + ni * 8 + 2 * t;
                float bx = bias[col], by = bias[col + 1];
                float2 v0 = { acc[mi][ni][0] + bx, acc[mi][ni][1] + by };
                float2 v1 = { acc[mi][ni][2] + bx, acc[mi][ni][3] + by };
                *(float2*)(out + (size_t)r0 * E_ + col) = v0;
                *(float2*)(out + (size_t)(r0 + 8) * E_ + col) = v1;
            }
        }
    }
}

// ==================== fused flash-MMA attention: 128-query blocks, 8 warps ====================
__global__ __launch_bounds__(256) void attn_mma() {
    __shared__ __align__(16) __half sQ[128 * 64];
    __shared__ __align__(16) __half sK[2][64 * 64];
    __shared__ __align__(16) __half sV[2][64 * 64];

    int bh = blockIdx.x;
    int batch = bh >> 4, h = bh & 15;
    int qt = blockIdx.y;
    int level = blockIdx.z;
    const int* sidx = &g_sidx[level][batch][0];
    int tid = threadIdx.x, wid = tid >> 5, lane = tid & 31;
    int g = lane >> 2, t = lane & 3;

    int C = (level == 0) ? 256 : (level == 1) ? 64 : 16;
    int q0 = qt * 128;
    int cg0 = q0 / C, cgL = (q0 + 127) / C;
    int klo = cg0 ? (cg0 - 1) * C : 0;
    int khi = (cgL + 1) * C;
    int ntiles = (khi - klo + 63) >> 6;
    int cg = (q0 + wid * 16) / C;
    int wlo = cg ? (cg - 1) * C : 0;
    int whi = (cg + 1) * C;

    int fc = tid & 7, fr = tid >> 3;
    uint32_t fcb = (uint32_t)(fc * 16);
    size_t hbase = (size_t)(batch * N_) * E_ + h * HD_;
    uint32_t sq = smem_u32(sQ);
    uint32_t skb[2] = { smem_u32(sK[0]), smem_u32(sK[1]) };
    uint32_t svb[2] = { smem_u32(sV[0]), smem_u32(sV[1]) };

    auto load_kv = [&](int buf, int tile) {
#pragma unroll
        for (int p = 0; p < 2; p++) {
            int row = p * 32 + fr;
            int pos = klo + tile * 64 + row;
            int tok = sidx[min(pos, N_ - 1)];
            uint32_t off = (uint32_t)(row * 128) + (fcb ^ ((uint32_t)(row & 7) << 4));
            cp16(skb[buf] + off, (const uint4*)(g_kh + hbase + (size_t)tok * E_) + fc);
            cp16(svb[buf] + off, (const uint4*)(g_vh + hbase + (size_t)tok * E_) + fc);
        }
        CP_COMMIT();
    };

#pragma unroll
    for (int p = 0; p < 4; p++) {
        int row = p * 32 + fr;
        int tok = sidx[q0 + row];
        uint32_t off = (uint32_t)(row * 128) + (fcb ^ ((uint32_t)(row & 7) << 4));
        cp16(sq + off, (const uint4*)(g_qh + hbase + (size_t)tok * E_) + fc);
    }
    load_kv(0, 0);

    int lane7 = lane & 7, st = lane >> 3;
    int kbrow = (st >> 1) * 8 + lane7;
    uint32_t kbcol = (uint32_t)((st & 1) * 16);
    int vrow = (st & 1) * 8 + lane7;
    uint32_t vcol = (uint32_t)((lane >> 4) * 16);

    uint32_t aq[4][4];
    float o[8][4];
#pragma unroll
    for (int i = 0; i < 8; i++)
#pragma unroll
        for (int j = 0; j < 4; j++) o[i][j] = 0.f;
    float m0 = -1e30f, m1 = -1e30f, l0 = 0.f, l1 = 0.f;

    for (int tile = 0; tile < ntiles; tile++) {
        int buf = tile & 1;
        CP_WAIT(0);
        __syncthreads();
        if (tile == 0) {
            int arow = wid * 16 + (st & 1) * 8 + lane7;
            uint32_t acol = (uint32_t)((st >> 1) * 16);
#pragma unroll
            for (int kk = 0; kk < 4; kk++) {
                uint32_t off = (uint32_t)(arow * 128) + ((acol + kk * 32) ^ ((uint32_t)(arow & 7) << 4));
                ldsm4(sq + off, aq[kk]);
            }
        }
        if (tile + 1 < ntiles) load_kv(buf ^ 1, tile + 1);

        int tlo = klo + tile * 64;
        bool active = (wlo < tlo + 64) && (whi > tlo);
        bool partial = (wlo > tlo) || (whi < tlo + 64);
        if (active) {
            uint32_t sk = skb[buf], sv = svb[buf];
            float c[8][4];
#pragma unroll
            for (int i = 0; i < 8; i++)
#pragma unroll
                for (int j = 0; j < 4; j++) c[i][j] = 0.f;
#pragma unroll
            for (int kk = 0; kk < 4; kk++) {
                uint32_t ko2 = (uint32_t)(kk * 32);
#pragma unroll
                for (int nt = 0; nt < 4; nt++) {
                    int row = nt * 16 + kbrow;
                    uint32_t off = (uint32_t)(row * 128) + ((ko2 + kbcol) ^ ((uint32_t)(row & 7) << 4));
                    uint32_t bf[4];
                    ldsm4(sk + off, bf);
                    mma16816(c[2 * nt],     aq[kk], bf[0], bf[1]);
                    mma16816(c[2 * nt + 1], aq[kk], bf[2], bf[3]);
                }
            }
            if (partial) {
#pragma unroll
                for (int nt = 0; nt < 8; nt++) {
                    int col0 = tlo + nt * 8 + 2 * t;
                    if (col0 < wlo || col0 >= whi)         { c[nt][0] = -1e30f; c[nt][2] = -1e30f; }
                    if (col0 + 1 < wlo || col0 + 1 >= whi) { c[nt][1] = -1e30f; c[nt][3] = -1e30f; }
                }
            }
            float mx0 = -1e30f, mx1 = -1e30f;
#pragma unroll
            for (int nt = 0; nt < 8; nt++) {
                mx0 = fmaxf(mx0, fmaxf(c[nt][0], c[nt][1]));
                mx1 = fmaxf(mx1, fmaxf(c[nt][2], c[nt][3]));
            }
            mx0 = fmaxf(mx0, __shfl_xor_sync(0xFFFFFFFFu, mx0, 1));
            mx0 = fmaxf(mx0, __shfl_xor_sync(0xFFFFFFFFu, mx0, 2));
            mx1 = fmaxf(mx1, __shfl_xor_sync(0xFFFFFFFFu, mx1, 1));
            mx1 = fmaxf(mx1, __shfl_xor_sync(0xFFFFFFFFu, mx1, 2));
            float mn0 = fmaxf(m0, mx0), mn1 = fmaxf(m1, mx1);
            float cr0 = exp2f(m0 - mn0), cr1 = exp2f(m1 - mn1);
            m0 = mn0; m1 = mn1;
            l0 *= cr0; l1 *= cr1;
            uint32_t pA[8], pB[8];
#pragma unroll
            for (int nt = 0; nt < 8; nt++) {
                float e0 = exp2f(c[nt][0] - m0), e1 = exp2f(c[nt][1] - m0);
                float e2 = exp2f(c[nt][2] - m1), e3 = exp2f(c[nt][3] - m1);
                l0 += e0 + e1; l1 += e2 + e3;
                pA[nt] = packh2(e0, e1);
                pB[nt] = packh2(e2, e3);
            }
#pragma unroll
            for (int ht = 0; ht < 8; ht++) {
                o[ht][0] *= cr0; o[ht][1] *= cr0;
                o[ht][2] *= cr1; o[ht][3] *= cr1;
            }
#pragma unroll
            for (int kj = 0; kj < 4; kj++) {
                uint32_t a[4] = { pA[2 * kj], pB[2 * kj], pA[2 * kj + 1], pB[2 * kj + 1] };
#pragma unroll
                for (int ht = 0; ht < 4; ht++) {
                    int row = kj * 16 + vrow;
                    uint32_t off = (uint32_t)(row * 128) +
                                   (((uint32_t)(ht * 32) + vcol) ^ ((uint32_t)(row & 7) << 4));
                    uint32_t b[4];
                    ldsm4t(sv + off, b);
                    mma16816(o[2 * ht],     a, b[0], b[1]);
                    mma16816(o[2 * ht + 1], a, b[2], b[3]);
                }
            }
        }
        __syncthreads();
    }

    l0 += __shfl_xor_sync(0xFFFFFFFFu, l0, 1);
    l0 += __shfl_xor_sync(0xFFFFFFFFu, l0, 2);
    l1 += __shfl_xor_sync(0xFFFFFFFFu, l1, 1);
    l1 += __shfl_xor_sync(0xFFFFFFFFu, l1, 2);
    float inv0 = 1.f / (3.f * l0);
    float inv1 = 1.f / (3.f * l1);

    int pq0 = q0 + wid * 16 + g;
    int tok0 = sidx[pq0];
    int tok1 = sidx[pq0 + 8];
    __half* base = g_attn3[level];
    __half* d0 = base + (size_t)(batch * N_ + tok0) * E_ + h * HD_;
    __half* d1 = base + (size_t)(batch * N_ + tok1) * E_ + h * HD_;
#pragma unroll
    for (int nt = 0; nt < 8; nt++) {
        int col = nt * 8 + 2 * t;
        *(__half2*)(d0 + col) = __floats2half2_rn(o[nt][0] * inv0, o[nt][1] * inv0);
        *(__half2*)(d1 + col) = __floats2half2_rn(o[nt][2] * inv1, o[nt][3] * inv1);
    }
}

// ==================== launch ====================
extern "C" void kernel_launch(void* const* d_in, const int* in_sizes, int n_in,
                              void* d_out, int out_size) {
    (void)in_sizes; (void)n_in; (void)out_size;
    const float* x   = (const float*)d_in[0];
    const int*   wbc = (const int*)d_in[1];
    const int*   wbm = (const int*)d_in[2];
    const int*   wbf = (const int*)d_in[3];
    const float* Wp[4] = { (const float*)d_in[4],  (const float*)d_in[8],
                           (const float*)d_in[12], (const float*)d_in[16] };
    const float* bp[4] = { (const float*)d_in[5],  (const float*)d_in[9],
                           (const float*)d_in[13], (const float*)d_in[17] };
    const float* Ap[4] = { (const float*)d_in[6],  (const float*)d_in[10],
                           (const float*)d_in[14], (const float*)d_in[18] };
    const float* Lp[4] = { (const float*)d_in[7],  (const float*)d_in[11],
                           (const float*)d_in[15], (const float*)d_in[19] };
    float* out = (float*)d_out;

    cudaFuncSetAttribute(gemm_tc, cudaFuncAttributeMaxDynamicSharedMemorySize, GEMM_SMEM);
    cudaFuncSetAttribute(sort_kernel, cudaFuncAttributeMaxDynamicSharedMemorySize, SORT_SMEM);

    // 1) fused LoRA fold (fp16) + x->fp16
    prep_kernel<<<dim3(4096, 6), 256>>>(
        Wp[0], Ap[0], Lp[0], Wp[1], Ap[1], Lp[1],
        Wp[2], Ap[2], Lp[2], Wp[3], Ap[3], Lp[3], x);

    // 2) fused q,k,v projections (single-product fp16)
    gemm_tc<<<dim3(M_ / 128, E_ / 128, 3), 256, GEMM_SMEM>>>(1, bp[0], bp[1], bp[2], nullptr);

    // 3) stable counting sort per (batch, level)
    sort_kernel<<<dim3(B_, 3), 256, SORT_SMEM>>>(wbc, wbm, wbf);

    // 4) fused three-level flash-MMA attention (fp16 per-level outputs)
    attn_mma<<<dim3(BH_, N_ / 128, 3), 256>>>();

    // 5) sum levels (fp16 in) -> fp16
    cvt_sum_kernel<<<(MSZ / 8) / 256, 256>>>();

    // 6) output projection
    gemm_tc<<<dim3(M_ / 128, E_ / 128, 1), 256, GEMM_SMEM>>>(0, bp[3], nullptr, nullptr, out);
}